// round 13
// baseline (speedup 1.0000x reference)
#include <cuda_runtime.h>
#include <cuda_fp16.h>
#include <cstdint>
#include <cstring>

// Problem constants
#define B_   4
#define T_   2048
#define C_   1024
#define H_   16
#define DH_  64
#define M_   (B_ * T_)          // 8192
#define N_QKV (3 * C_)          // 3072
#define K_   1024

#define LOG2E 1.4426950408889634f

// ---------------------------------------------------------------------------
// Device-global scratch
// ---------------------------------------------------------------------------
__device__ __half g_qh[B_ * H_ * T_ * DH_];
__device__ __half g_kh[B_ * H_ * T_ * DH_];
__device__ __half g_vh[B_ * H_ * T_ * DH_];
__device__ __half g_xh[M_ * K_];
__device__ __half g_yh[M_ * C_];
__device__ __half g_wqkvT[N_QKV * K_];   // [N][K]
__device__ __half g_wprojT[C_ * K_];

#define SMEM_SWIZZLE_128B(o) ((o) ^ (((o) >> 3) & 0x70))

__device__ __forceinline__ uint32_t smem_to_u32(const void* p) {
    uint32_t a;
    asm("{ .reg .u64 t; cvta.to.shared.u64 t, %1; cvt.u32.u64 %0, t; }" : "=r"(a) : "l"(p));
    return a;
}
__device__ __forceinline__ void cp16(uint32_t saddr, const void* g) {
    asm volatile("cp.async.cg.shared.global [%0], [%1], 16;" :: "r"(saddr), "l"(g));
}
__device__ __forceinline__ void cp_commit() {
    asm volatile("cp.async.commit_group;" ::: "memory");
}
__device__ __forceinline__ void ldsm_x4(uint32_t* r, uint32_t addr) {
    asm volatile("ldmatrix.sync.aligned.m8n8.x4.shared.b16 {%0,%1,%2,%3}, [%4];"
        : "=r"(r[0]), "=r"(r[1]), "=r"(r[2]), "=r"(r[3]) : "r"(addr));
}
__device__ __forceinline__ void ldsm_x4_trans(uint32_t* r, uint32_t addr) {
    asm volatile("ldmatrix.sync.aligned.m8n8.x4.trans.shared.b16 {%0,%1,%2,%3}, [%4];"
        : "=r"(r[0]), "=r"(r[1]), "=r"(r[2]), "=r"(r[3]) : "r"(addr));
}
__device__ __forceinline__ void mma_f16(float* c, const uint32_t* a, const uint32_t* b) {
    asm volatile("mma.sync.aligned.m16n8k16.row.col.f32.f16.f16.f32 "
        "{%0,%1,%2,%3}, {%4,%5,%6,%7}, {%8,%9}, {%0,%1,%2,%3};"
        : "+f"(c[0]), "+f"(c[1]), "+f"(c[2]), "+f"(c[3])
        : "r"(a[0]), "r"(a[1]), "r"(a[2]), "r"(a[3]), "r"(b[0]), "r"(b[1]));
}
__device__ __forceinline__ uint32_t pack_h2(float lo, float hi) {
    __half2 h = __floats2half2_rn(lo, hi);
    uint32_t u; memcpy(&u, &h, 4); return u;
}
__device__ __forceinline__ float ex2(float x) {
    float r;
    asm("ex2.approx.ftz.f32 %0, %1;" : "=f"(r) : "f"(x));
    return r;
}

// ---------------------------------------------------------------------------
// Fused prep kernel (blockIdx-partitioned)
// ---------------------------------------------------------------------------
#define PREP_X_BLOCKS  (M_ * K_ / (256 * 4))          // 8192
#define PREP_WQ_BLOCKS ((N_QKV / 32) * (K_ / 32))     // 3072
#define PREP_WP_BLOCKS ((C_ / 32) * (K_ / 32))        // 1024
#define PREP_BLOCKS (PREP_X_BLOCKS + PREP_WQ_BLOCKS + PREP_WP_BLOCKS)

__global__ __launch_bounds__(256) void prep_kernel(
    const float* __restrict__ x,
    const float* __restrict__ wqkv,
    const float* __restrict__ wproj)
{
    __shared__ float t[32][33];
    int bid = blockIdx.x;
    int tid = threadIdx.x;

    if (bid < PREP_X_BLOCKS) {
        int idx = (bid * 256 + tid) * 4;
        float4 v = *(const float4*)(x + idx);
        float vv[4] = {v.x, v.y, v.z, v.w};
        __half h[4];
#pragma unroll
        for (int i = 0; i < 4; i++) h[i] = __float2half_rn(vv[i]);
        *(uint2*)(g_xh + idx) = *(uint2*)h;
        return;
    }

    const float* W;
    __half* WT;
    int N, bx, by;
    if (bid < PREP_X_BLOCKS + PREP_WQ_BLOCKS) {
        int b = bid - PREP_X_BLOCKS;
        W = wqkv; WT = g_wqkvT; N = N_QKV;
        bx = b % (N_QKV / 32); by = b / (N_QKV / 32);
    } else {
        int b = bid - PREP_X_BLOCKS - PREP_WQ_BLOCKS;
        W = wproj; WT = g_wprojT; N = C_;
        bx = b % (C_ / 32); by = b / (C_ / 32);
    }
    int n0 = bx * 32, k0 = by * 32;
    int tx = tid & 31, ty = tid >> 5;
#pragma unroll
    for (int i = 0; i < 4; i++)
        t[ty + i * 8][tx] = W[(size_t)(k0 + ty + i * 8) * N + n0 + tx];
    __syncthreads();
#pragma unroll
    for (int i = 0; i < 4; i++) {
        int n = n0 + ty + i * 8;
        int k = k0 + tx;
        WT[(size_t)n * K_ + k] = __float2half_rn(t[tx][ty + i * 8]);
    }
}

// ---------------------------------------------------------------------------
// Tensor-core GEMM, 1-term fp16, 3-stage single-sync pipeline.
// CTA tile 128x128, BK=64, 8 warps (2m x 4n), warp tile 64x32.
// Stage 32KB, 3 stages = 96KB -> 2 CTAs/SM.
// mode 0: scatter q (scaled by 0.125*log2e) / k / v; mode 1: f32 store.
// ---------------------------------------------------------------------------
#define STAGE_BYTES 32768
#define SM_GEMM_TOTAL (3 * STAGE_BYTES)   // 98304

__global__ __launch_bounds__(256, 2) void mma_gemm_kernel(
    const __half* __restrict__ Ah, const __half* __restrict__ Bm,
    float* __restrict__ out, int mode)
{
    extern __shared__ char smem[];
    uint32_t sbase = smem_to_u32(smem);

    int tid = threadIdx.x;
    int wid = tid >> 5;
    int lane = tid & 31;
    int wm = wid >> 2;
    int wn = wid & 3;

    int m0 = blockIdx.y * 128;
    int n0 = blockIdx.x * 128;

    float acc[4][4][4];
#pragma unroll
    for (int i = 0; i < 4; i++)
#pragma unroll
        for (int j = 0; j < 4; j++)
#pragma unroll
            for (int c = 0; c < 4; c++) acc[i][j][c] = 0.f;

    auto load_chunk = [&](int kt, int s) {
        uint32_t st = sbase + s * STAGE_BYTES;
#pragma unroll
        for (int p = 0; p < 4; p++) {
            int idx = tid + p * 256;
            int row = idx >> 3;
            int ch  = idx & 7;
            uint32_t so = SMEM_SWIZZLE_128B(row * 128 + ch * 16);
            size_t ka = (size_t)(m0 + row) * K_ + kt * 64 + ch * 8;
            size_t kb = (size_t)(n0 + row) * K_ + kt * 64 + ch * 8;
            cp16(st + so,         Ah + ka);
            cp16(st + 16384 + so, Bm + kb);
        }
        cp_commit();
    };

    load_chunk(0, 0);
    load_chunk(1, 1);

    int a_row = lane & 15;
    int a_cb  = (lane >> 4) << 4;
    int bg     = lane >> 3;
    int bp_row = (lane & 7) + ((bg >> 1) << 3);
    int bp_cb  = (bg & 1) << 4;

    for (int kt = 0; kt < 16; kt++) {
        int s = kt % 3;
        if (kt + 1 < 16)
            asm volatile("cp.async.wait_group 1;" ::: "memory");
        else
            asm volatile("cp.async.wait_group 0;" ::: "memory");
        __syncthreads();
        if (kt + 2 < 16) load_chunk(kt + 2, (kt + 2) % 3);

        uint32_t sA = sbase + s * STAGE_BYTES;
        uint32_t sB = sA + 16384;

#pragma unroll
        for (int ks = 0; ks < 4; ks++) {
            int kB = ks * 32;
            uint32_t ah[4][4], bh[4][2];
#pragma unroll
            for (int i = 0; i < 4; i++) {
                uint32_t off = SMEM_SWIZZLE_128B((wm * 64 + i * 16 + a_row) * 128 + kB + a_cb);
                ldsm_x4(ah[i], sA + off);
            }
#pragma unroll
            for (int jp = 0; jp < 2; jp++) {
                uint32_t off = SMEM_SWIZZLE_128B((wn * 32 + jp * 16 + bp_row) * 128 + kB + bp_cb);
                uint32_t r4[4];
                ldsm_x4(r4, sB + off);
                bh[2 * jp][0] = r4[0]; bh[2 * jp][1] = r4[1];
                bh[2 * jp + 1][0] = r4[2]; bh[2 * jp + 1][1] = r4[3];
            }
#pragma unroll
            for (int i = 0; i < 4; i++)
#pragma unroll
                for (int j = 0; j < 4; j++) mma_f16(acc[i][j], ah[i], bh[j]);
        }
    }

    int r4i = lane >> 2;
    int cp2 = (lane & 3) * 2;

    if (mode == 1) {
#pragma unroll
        for (int i = 0; i < 4; i++)
#pragma unroll
            for (int j = 0; j < 4; j++) {
                int n = n0 + wn * 32 + j * 8 + cp2;
#pragma unroll
                for (int rr = 0; rr < 2; rr++) {
                    int m = m0 + wm * 64 + i * 16 + r4i + rr * 8;
                    *(float2*)(out + (size_t)m * C_ + n) =
                        make_float2(acc[i][j][rr * 2], acc[i][j][rr * 2 + 1]);
                }
            }
    } else {
        int which = n0 >> 10;
        __half* dst = (which == 0) ? g_qh : (which == 1) ? g_kh : g_vh;
        float scale = (which == 0) ? (0.125f * LOG2E) : 1.0f;  // fold log2e into q
#pragma unroll
        for (int i = 0; i < 4; i++)
#pragma unroll
            for (int j = 0; j < 4; j++) {
                int n = n0 + wn * 32 + j * 8 + cp2;
                int h = (n & 1023) >> 6;
                int d = n & 63;
#pragma unroll
                for (int rr = 0; rr < 2; rr++) {
                    int m = m0 + wm * 64 + i * 16 + r4i + rr * 8;
                    int b = m >> 11;
                    int t = m & 2047;
                    size_t off = (size_t)(((b << 4) + h) * T_ + t) * DH_ + d;
                    *(uint32_t*)(dst + off) =
                        pack_h2(acc[i][j][rr * 2] * scale, acc[i][j][rr * 2 + 1] * scale);
                }
            }
    }
}

// ---------------------------------------------------------------------------
// Tensor-core causal flash attention — 1-term fp16, 3-stage single-sync.
// S is in log2 domain (q pre-scaled by 0.125*log2e); softmax via ex2.approx.
// Smem: Q(16K) + 3 x (K8|V8) = 64K -> 2 CTAs/SM. LPT grid.
// ---------------------------------------------------------------------------
#define AS_Q  0
#define AS_KV 16384
#define AS_TOTAL (16384 + 3 * 16384)   // 65536

__global__ __launch_bounds__(256, 2) void attn_mma_kernel()
{
    extern __shared__ char smem[];
    uint32_t sb = smem_to_u32(smem);
    int tid = threadIdx.x;
    int wid = tid >> 5;
    int lane = tid & 31;

    int qt = 15 - blockIdx.y;     // longest first
    int bh = blockIdx.x;
    int q0 = qt * 128;
    size_t base = (size_t)bh * T_ * DH_;
    int nkt = 2 * qt + 2;

    auto load_kv = [&](int j, int s) {
        uint32_t st = sb + AS_KV + s * 16384;
#pragma unroll
        for (int p = 0; p < 2; p++) {
            int idx = tid + p * 256;
            int row = idx >> 3;
            int ch  = idx & 7;
            uint32_t so = SMEM_SWIZZLE_128B(row * 128 + ch * 16);
            size_t g = base + (size_t)(j * 64 + row) * DH_ + ch * 8;
            cp16(st + so,        g_kh + g);
            cp16(st + 8192 + so, g_vh + g);
        }
        cp_commit();
    };

    // prologue: Q + kv0 in one group, kv1 second group
#pragma unroll
    for (int p = 0; p < 4; p++) {
        int idx = tid + p * 256;
        int row = idx >> 3;
        int ch  = idx & 7;
        uint32_t so = SMEM_SWIZZLE_128B(row * 128 + ch * 16);
        cp16(sb + AS_Q + so, g_qh + base + (size_t)(q0 + row) * DH_ + ch * 8);
    }
    {
        uint32_t st = sb + AS_KV;   // stage 0
#pragma unroll
        for (int p = 0; p < 2; p++) {
            int idx = tid + p * 256;
            int row = idx >> 3;
            int ch  = idx & 7;
            uint32_t so = SMEM_SWIZZLE_128B(row * 128 + ch * 16);
            size_t g = base + (size_t)(row) * DH_ + ch * 8;
            cp16(st + so,        g_kh + g);
            cp16(st + 8192 + so, g_vh + g);
        }
        cp_commit();
    }
    if (nkt > 1) load_kv(1, 1);

    uint32_t qh[4][4];
    float O[8][4];
#pragma unroll
    for (int dt = 0; dt < 8; dt++)
#pragma unroll
        for (int c = 0; c < 4; c++) O[dt][c] = 0.f;
    float m0r = -1e30f, m1r = -1e30f, l0r = 0.f, l1r = 0.f;

    int g4 = lane >> 2;
    int c2 = 2 * (lane & 3);
    int a_row = lane & 15;
    int a_cb  = (lane >> 4) << 4;
    int bg     = lane >> 3;
    int bp_row = (lane & 7) + ((bg >> 1) << 3);
    int bp_cb  = (bg & 1) << 4;
    int v_row = (lane & 7) + ((lane >> 3) & 1) * 8;
    int v_ct  = (lane >> 4) & 1;

    for (int j = 0; j < nkt; j++) {
        int s = j % 3;
        if (j + 1 < nkt)
            asm volatile("cp.async.wait_group 1;" ::: "memory");
        else
            asm volatile("cp.async.wait_group 0;" ::: "memory");
        __syncthreads();
        if (j + 2 < nkt) load_kv(j + 2, (j + 2) % 3);

        if (j == 0) {
#pragma unroll
            for (int ks = 0; ks < 4; ks++) {
                uint32_t off = SMEM_SWIZZLE_128B((wid * 16 + a_row) * 128 + ks * 32 + a_cb);
                ldsm_x4(qh[ks], sb + AS_Q + off);
            }
        }

        uint32_t stK = sb + AS_KV + s * 16384;
        uint32_t stV = stK + 8192;

        // ---- S = Q @ K^T (log2 domain) ----
        float S[8][4];
#pragma unroll
        for (int jt = 0; jt < 8; jt++)
#pragma unroll
            for (int c = 0; c < 4; c++) S[jt][c] = 0.f;

#pragma unroll
        for (int jp = 0; jp < 4; jp++) {
#pragma unroll
            for (int ks = 0; ks < 4; ks++) {
                uint32_t off = SMEM_SWIZZLE_128B((jp * 16 + bp_row) * 128 + ks * 32 + bp_cb);
                uint32_t r4[4];
                ldsm_x4(r4, stK + off);
                mma_f16(S[2 * jp],     qh[ks], r4);
                mma_f16(S[2 * jp + 1], qh[ks], r4 + 2);
            }
        }

        if (j >= 2 * qt) {
            int r0 = q0 + wid * 16 + g4;
            int cb = j * 64 + c2;
#pragma unroll
            for (int jt = 0; jt < 8; jt++) {
                int c0 = cb + jt * 8;
                if (c0 > r0)     S[jt][0] = -1e30f;
                if (c0 + 1 > r0) S[jt][1] = -1e30f;
                if (c0 > r0 + 8)     S[jt][2] = -1e30f;
                if (c0 + 1 > r0 + 8) S[jt][3] = -1e30f;
            }
        }

        float mx0 = -1e30f, mx1 = -1e30f;
#pragma unroll
        for (int jt = 0; jt < 8; jt++) {
            mx0 = fmaxf(mx0, fmaxf(S[jt][0], S[jt][1]));
            mx1 = fmaxf(mx1, fmaxf(S[jt][2], S[jt][3]));
        }
        mx0 = fmaxf(mx0, __shfl_xor_sync(0xffffffffu, mx0, 1));
        mx0 = fmaxf(mx0, __shfl_xor_sync(0xffffffffu, mx0, 2));
        mx1 = fmaxf(mx1, __shfl_xor_sync(0xffffffffu, mx1, 1));
        mx1 = fmaxf(mx1, __shfl_xor_sync(0xffffffffu, mx1, 2));

        float mn0 = fmaxf(m0r, mx0), mn1 = fmaxf(m1r, mx1);
        float al0 = ex2(m0r - mn0), al1 = ex2(m1r - mn1);
        m0r = mn0; m1r = mn1;

        float s0 = 0.f, s1 = 0.f;
#pragma unroll
        for (int jt = 0; jt < 8; jt++) {
            S[jt][0] = ex2(S[jt][0] - mn0); s0 += S[jt][0];
            S[jt][1] = ex2(S[jt][1] - mn0); s0 += S[jt][1];
            S[jt][2] = ex2(S[jt][2] - mn1); s1 += S[jt][2];
            S[jt][3] = ex2(S[jt][3] - mn1); s1 += S[jt][3];
        }
        s0 += __shfl_xor_sync(0xffffffffu, s0, 1);
        s0 += __shfl_xor_sync(0xffffffffu, s0, 2);
        s1 += __shfl_xor_sync(0xffffffffu, s1, 1);
        s1 += __shfl_xor_sync(0xffffffffu, s1, 2);
        l0r = l0r * al0 + s0;
        l1r = l1r * al1 + s1;

#pragma unroll
        for (int dt = 0; dt < 8; dt++) {
            O[dt][0] *= al0; O[dt][1] *= al0;
            O[dt][2] *= al1; O[dt][3] *= al1;
        }

        // ---- pack P (fp16) in place ----
#pragma unroll
        for (int ks2 = 0; ks2 < 4; ks2++) {
#pragma unroll
            for (int q = 0; q < 4; q++) {
                int tile = 2 * ks2 + (q >> 1);
                int cb = (q & 1) * 2;
                S[tile][cb] = __uint_as_float(pack_h2(S[tile][cb], S[tile][cb + 1]));
            }
        }

        // ---- O += P @ V ----
#pragma unroll
        for (int dtp = 0; dtp < 4; dtp++) {
#pragma unroll
            for (int ks2 = 0; ks2 < 4; ks2++) {
                uint32_t ph[4] = {
                    __float_as_uint(S[2 * ks2][0]),     __float_as_uint(S[2 * ks2][2]),
                    __float_as_uint(S[2 * ks2 + 1][0]), __float_as_uint(S[2 * ks2 + 1][2])};
                uint32_t off = SMEM_SWIZZLE_128B((ks2 * 16 + v_row) * 128 +
                                                 (2 * dtp + v_ct) * 16);
                uint32_t r4[4];
                ldsm_x4_trans(r4, stV + off);
                mma_f16(O[2 * dtp],     ph, r4);
                mma_f16(O[2 * dtp + 1], ph, r4 + 2);
            }
        }
    }

    // ---- epilogue: y = O / l, fp16 ----
    float li0 = 1.f / l0r, li1 = 1.f / l1r;
    int b = bh >> 4, h = bh & 15;
    int r0 = q0 + wid * 16 + g4;
#pragma unroll
    for (int dt = 0; dt < 8; dt++) {
        int d = dt * 8 + c2;
        {
            size_t off = (size_t)(b * T_ + r0) * C_ + h * DH_ + d;
            *(uint32_t*)(g_yh + off) = pack_h2(O[dt][0] * li0, O[dt][1] * li0);
        }
        {
            size_t off = (size_t)(b * T_ + r0 + 8) * C_ + h * DH_ + d;
            *(uint32_t*)(g_yh + off) = pack_h2(O[dt][2] * li1, O[dt][3] * li1);
        }
    }
}

// ---------------------------------------------------------------------------
extern "C" void kernel_launch(void* const* d_in, const int* in_sizes, int n_in,
                              void* d_out, int out_size)
{
    const float* x      = (const float*)d_in[0];
    const float* w_qkv  = (const float*)d_in[1];
    const float* w_proj = (const float*)d_in[2];
    float* out = (float*)d_out;
    (void)in_sizes; (void)n_in; (void)out_size;

    cudaFuncSetAttribute(mma_gemm_kernel,
                         cudaFuncAttributeMaxDynamicSharedMemorySize, SM_GEMM_TOTAL);
    cudaFuncSetAttribute(attn_mma_kernel,
                         cudaFuncAttributeMaxDynamicSharedMemorySize, AS_TOTAL);

    __half *xh, *yh, *wq, *wp;
    cudaGetSymbolAddress((void**)&xh, g_xh);
    cudaGetSymbolAddress((void**)&yh, g_yh);
    cudaGetSymbolAddress((void**)&wq, g_wqkvT);
    cudaGetSymbolAddress((void**)&wp, g_wprojT);

    // fused prep
    prep_kernel<<<PREP_BLOCKS, 256>>>(x, w_qkv, w_proj);

    // QKV GEMM (1-term) with fused q-scale(+log2e) + scatter
    mma_gemm_kernel<<<dim3(N_QKV / 128, M_ / 128), 256, SM_GEMM_TOTAL>>>(
        xh, wq, nullptr, 0);

    // tensor-core causal flash attention
    attn_mma_kernel<<<dim3(B_ * H_, T_ / 128), 256, AS_TOTAL>>>();

    // output projection GEMM (1-term)
    mma_gemm_kernel<<<dim3(C_ / 128, M_ / 128), 256, SM_GEMM_TOTAL>>>(
        yh, wp, out, 1);
}

// round 14
// speedup vs baseline: 1.5049x; 1.5049x over previous
#include <cuda_runtime.h>
#include <cuda_fp16.h>
#include <cstdint>
#include <cstring>

// Problem constants
#define B_   4
#define T_   2048
#define C_   1024
#define H_   16
#define DH_  64
#define M_   (B_ * T_)          // 8192
#define N_QKV (3 * C_)          // 3072
#define K_   1024

#define LOG2E 1.4426950408889634f

// ---------------------------------------------------------------------------
// Device-global scratch
// ---------------------------------------------------------------------------
__device__ __half g_qh[B_ * H_ * T_ * DH_];
__device__ __half g_kh[B_ * H_ * T_ * DH_];
__device__ __half g_vh[B_ * H_ * T_ * DH_];
__device__ __half g_xh[M_ * K_];
__device__ __half g_yh[M_ * C_];
__device__ __half g_wqkvT[N_QKV * K_];   // [N][K]
__device__ __half g_wprojT[C_ * K_];

#define SMEM_SWIZZLE_128B(o) ((o) ^ (((o) >> 3) & 0x70))

__device__ __forceinline__ uint32_t smem_to_u32(const void* p) {
    uint32_t a;
    asm("{ .reg .u64 t; cvta.to.shared.u64 t, %1; cvt.u32.u64 %0, t; }" : "=r"(a) : "l"(p));
    return a;
}
__device__ __forceinline__ void cp16(uint32_t saddr, const void* g) {
    asm volatile("cp.async.cg.shared.global [%0], [%1], 16;" :: "r"(saddr), "l"(g));
}
__device__ __forceinline__ void cp_commit() {
    asm volatile("cp.async.commit_group;" ::: "memory");
}
__device__ __forceinline__ void ldsm_x4(uint32_t* r, uint32_t addr) {
    asm volatile("ldmatrix.sync.aligned.m8n8.x4.shared.b16 {%0,%1,%2,%3}, [%4];"
        : "=r"(r[0]), "=r"(r[1]), "=r"(r[2]), "=r"(r[3]) : "r"(addr));
}
__device__ __forceinline__ void ldsm_x4_trans(uint32_t* r, uint32_t addr) {
    asm volatile("ldmatrix.sync.aligned.m8n8.x4.trans.shared.b16 {%0,%1,%2,%3}, [%4];"
        : "=r"(r[0]), "=r"(r[1]), "=r"(r[2]), "=r"(r[3]) : "r"(addr));
}
__device__ __forceinline__ void mma_f16(float* c, const uint32_t* a, const uint32_t* b) {
    asm volatile("mma.sync.aligned.m16n8k16.row.col.f32.f16.f16.f32 "
        "{%0,%1,%2,%3}, {%4,%5,%6,%7}, {%8,%9}, {%0,%1,%2,%3};"
        : "+f"(c[0]), "+f"(c[1]), "+f"(c[2]), "+f"(c[3])
        : "r"(a[0]), "r"(a[1]), "r"(a[2]), "r"(a[3]), "r"(b[0]), "r"(b[1]));
}
__device__ __forceinline__ uint32_t pack_h2(float lo, float hi) {
    __half2 h = __floats2half2_rn(lo, hi);
    uint32_t u; memcpy(&u, &h, 4); return u;
}
__device__ __forceinline__ float ex2(float x) {
    float r;
    asm("ex2.approx.ftz.f32 %0, %1;" : "=f"(r) : "f"(x));
    return r;
}

// ---------------------------------------------------------------------------
// Fused prep kernel (blockIdx-partitioned) — identical to R12
// ---------------------------------------------------------------------------
#define PREP_X_BLOCKS  (M_ * K_ / (256 * 4))          // 8192
#define PREP_WQ_BLOCKS ((N_QKV / 32) * (K_ / 32))     // 3072
#define PREP_WP_BLOCKS ((C_ / 32) * (K_ / 32))        // 1024
#define PREP_BLOCKS (PREP_X_BLOCKS + PREP_WQ_BLOCKS + PREP_WP_BLOCKS)

__global__ __launch_bounds__(256) void prep_kernel(
    const float* __restrict__ x,
    const float* __restrict__ wqkv,
    const float* __restrict__ wproj)
{
    __shared__ float t[32][33];
    int bid = blockIdx.x;
    int tid = threadIdx.x;

    if (bid < PREP_X_BLOCKS) {
        int idx = (bid * 256 + tid) * 4;
        float4 v = *(const float4*)(x + idx);
        float vv[4] = {v.x, v.y, v.z, v.w};
        __half h[4];
#pragma unroll
        for (int i = 0; i < 4; i++) h[i] = __float2half_rn(vv[i]);
        *(uint2*)(g_xh + idx) = *(uint2*)h;
        return;
    }

    const float* W;
    __half* WT;
    int N, bx, by;
    if (bid < PREP_X_BLOCKS + PREP_WQ_BLOCKS) {
        int b = bid - PREP_X_BLOCKS;
        W = wqkv; WT = g_wqkvT; N = N_QKV;
        bx = b % (N_QKV / 32); by = b / (N_QKV / 32);
    } else {
        int b = bid - PREP_X_BLOCKS - PREP_WQ_BLOCKS;
        W = wproj; WT = g_wprojT; N = C_;
        bx = b % (C_ / 32); by = b / (C_ / 32);
    }
    int n0 = bx * 32, k0 = by * 32;
    int tx = tid & 31, ty = tid >> 5;
#pragma unroll
    for (int i = 0; i < 4; i++)
        t[ty + i * 8][tx] = W[(size_t)(k0 + ty + i * 8) * N + n0 + tx];
    __syncthreads();
#pragma unroll
    for (int i = 0; i < 4; i++) {
        int n = n0 + ty + i * 8;
        int k = k0 + tx;
        WT[(size_t)n * K_ + k] = __float2half_rn(t[tx][ty + i * 8]);
    }
}

// ---------------------------------------------------------------------------
// Tensor-core GEMM — exact R12 pipeline (2-stage, load-before-wait, 2 syncs).
// CTA tile 128x128, BK=64, 8 warps (2m x 4n), warp tile 64x32.
// Stage 32KB, double-buffered 64KB -> 2 CTAs/SM.
// mode 0: scatter q (scaled by 0.125*log2e) / k / v; mode 1: f32 store.
// ---------------------------------------------------------------------------
#define STAGE_BYTES 32768
#define SM_GEMM_TOTAL (2 * STAGE_BYTES)   // 65536

__global__ __launch_bounds__(256, 2) void mma_gemm_kernel(
    const __half* __restrict__ Ah, const __half* __restrict__ Bm,
    float* __restrict__ out, int mode)
{
    extern __shared__ char smem[];
    uint32_t sbase = smem_to_u32(smem);

    int tid = threadIdx.x;
    int wid = tid >> 5;
    int lane = tid & 31;
    int wm = wid >> 2;
    int wn = wid & 3;

    int m0 = blockIdx.y * 128;
    int n0 = blockIdx.x * 128;

    float acc[4][4][4];
#pragma unroll
    for (int i = 0; i < 4; i++)
#pragma unroll
        for (int j = 0; j < 4; j++)
#pragma unroll
            for (int c = 0; c < 4; c++) acc[i][j][c] = 0.f;

    auto load_chunk = [&](int kt, int s) {
        uint32_t st = sbase + s * STAGE_BYTES;
#pragma unroll
        for (int p = 0; p < 4; p++) {
            int idx = tid + p * 256;
            int row = idx >> 3;
            int ch  = idx & 7;
            uint32_t so = SMEM_SWIZZLE_128B(row * 128 + ch * 16);
            size_t ka = (size_t)(m0 + row) * K_ + kt * 64 + ch * 8;
            size_t kb = (size_t)(n0 + row) * K_ + kt * 64 + ch * 8;
            cp16(st + so,         Ah + ka);
            cp16(st + 16384 + so, Bm + kb);
        }
        cp_commit();
    };

    load_chunk(0, 0);

    int a_row = lane & 15;
    int a_cb  = (lane >> 4) << 4;
    int bg     = lane >> 3;
    int bp_row = (lane & 7) + ((bg >> 1) << 3);
    int bp_cb  = (bg & 1) << 4;

    for (int kt = 0; kt < 16; kt++) {
        int s = kt & 1;
        if (kt + 1 < 16) {
            load_chunk(kt + 1, (kt + 1) & 1);
            asm volatile("cp.async.wait_group 1;" ::: "memory");
        } else {
            asm volatile("cp.async.wait_group 0;" ::: "memory");
        }
        __syncthreads();

        uint32_t sA = sbase + s * STAGE_BYTES;
        uint32_t sB = sA + 16384;

#pragma unroll
        for (int ks = 0; ks < 4; ks++) {
            int kB = ks * 32;
            uint32_t ah[4][4], bh[4][2];
#pragma unroll
            for (int i = 0; i < 4; i++) {
                uint32_t off = SMEM_SWIZZLE_128B((wm * 64 + i * 16 + a_row) * 128 + kB + a_cb);
                ldsm_x4(ah[i], sA + off);
            }
#pragma unroll
            for (int jp = 0; jp < 2; jp++) {
                uint32_t off = SMEM_SWIZZLE_128B((wn * 32 + jp * 16 + bp_row) * 128 + kB + bp_cb);
                uint32_t r4[4];
                ldsm_x4(r4, sB + off);
                bh[2 * jp][0] = r4[0]; bh[2 * jp][1] = r4[1];
                bh[2 * jp + 1][0] = r4[2]; bh[2 * jp + 1][1] = r4[3];
            }
#pragma unroll
            for (int i = 0; i < 4; i++)
#pragma unroll
                for (int j = 0; j < 4; j++) mma_f16(acc[i][j], ah[i], bh[j]);
        }
        __syncthreads();
    }

    int r4i = lane >> 2;
    int cp2 = (lane & 3) * 2;

    if (mode == 1) {
#pragma unroll
        for (int i = 0; i < 4; i++)
#pragma unroll
            for (int j = 0; j < 4; j++) {
                int n = n0 + wn * 32 + j * 8 + cp2;
#pragma unroll
                for (int rr = 0; rr < 2; rr++) {
                    int m = m0 + wm * 64 + i * 16 + r4i + rr * 8;
                    *(float2*)(out + (size_t)m * C_ + n) =
                        make_float2(acc[i][j][rr * 2], acc[i][j][rr * 2 + 1]);
                }
            }
    } else {
        int which = n0 >> 10;
        __half* dst = (which == 0) ? g_qh : (which == 1) ? g_kh : g_vh;
        float scale = (which == 0) ? (0.125f * LOG2E) : 1.0f;   // fold log2e into q
#pragma unroll
        for (int i = 0; i < 4; i++)
#pragma unroll
            for (int j = 0; j < 4; j++) {
                int n = n0 + wn * 32 + j * 8 + cp2;
                int h = (n & 1023) >> 6;
                int d = n & 63;
#pragma unroll
                for (int rr = 0; rr < 2; rr++) {
                    int m = m0 + wm * 64 + i * 16 + r4i + rr * 8;
                    int b = m >> 11;
                    int t = m & 2047;
                    size_t off = (size_t)(((b << 4) + h) * T_ + t) * DH_ + d;
                    *(uint32_t*)(dst + off) =
                        pack_h2(acc[i][j][rr * 2] * scale, acc[i][j][rr * 2 + 1] * scale);
                }
            }
    }
}

// ---------------------------------------------------------------------------
// Tensor-core causal flash attention — exact R12 pipeline, softmax via ex2
// (S already in log2 domain via the q pre-scale).
// Smem: Q(16K) + 2 x (K8|V8) = 48K -> 2 CTAs/SM. LPT grid.
// ---------------------------------------------------------------------------
#define AS_Q  0
#define AS_KV 16384
#define AS_TOTAL (16384 + 2 * 16384)   // 49152

__global__ __launch_bounds__(256, 2) void attn_mma_kernel()
{
    extern __shared__ char smem[];
    uint32_t sb = smem_to_u32(smem);
    int tid = threadIdx.x;
    int wid = tid >> 5;
    int lane = tid & 31;

    int qt = 15 - blockIdx.y;     // longest first
    int bh = blockIdx.x;
    int q0 = qt * 128;
    size_t base = (size_t)bh * T_ * DH_;
    int nkt = 2 * qt + 2;

#pragma unroll
    for (int p = 0; p < 4; p++) {
        int idx = tid + p * 256;
        int row = idx >> 3;
        int ch  = idx & 7;
        uint32_t so = SMEM_SWIZZLE_128B(row * 128 + ch * 16);
        cp16(sb + AS_Q + so, g_qh + base + (size_t)(q0 + row) * DH_ + ch * 8);
    }
    cp_commit();

    auto load_kv = [&](int j, int s) {
        uint32_t st = sb + AS_KV + s * 16384;
#pragma unroll
        for (int p = 0; p < 2; p++) {
            int idx = tid + p * 256;
            int row = idx >> 3;
            int ch  = idx & 7;
            uint32_t so = SMEM_SWIZZLE_128B(row * 128 + ch * 16);
            size_t g = base + (size_t)(j * 64 + row) * DH_ + ch * 8;
            cp16(st + so,        g_kh + g);
            cp16(st + 8192 + so, g_vh + g);
        }
        cp_commit();
    };

    load_kv(0, 0);

    uint32_t qh[4][4];
    float O[8][4];
#pragma unroll
    for (int dt = 0; dt < 8; dt++)
#pragma unroll
        for (int c = 0; c < 4; c++) O[dt][c] = 0.f;
    float m0r = -1e30f, m1r = -1e30f, l0r = 0.f, l1r = 0.f;

    int g4 = lane >> 2;
    int c2 = 2 * (lane & 3);
    int a_row = lane & 15;
    int a_cb  = (lane >> 4) << 4;
    int bg     = lane >> 3;
    int bp_row = (lane & 7) + ((bg >> 1) << 3);
    int bp_cb  = (bg & 1) << 4;
    int v_row = (lane & 7) + ((lane >> 3) & 1) * 8;
    int v_ct  = (lane >> 4) & 1;

    for (int j = 0; j < nkt; j++) {
        int s = j & 1;
        if (j + 1 < nkt) {
            load_kv(j + 1, (j + 1) & 1);
            asm volatile("cp.async.wait_group 1;" ::: "memory");
        } else {
            asm volatile("cp.async.wait_group 0;" ::: "memory");
        }
        __syncthreads();

        if (j == 0) {
#pragma unroll
            for (int ks = 0; ks < 4; ks++) {
                uint32_t off = SMEM_SWIZZLE_128B((wid * 16 + a_row) * 128 + ks * 32 + a_cb);
                ldsm_x4(qh[ks], sb + AS_Q + off);
            }
        }

        uint32_t stK = sb + AS_KV + s * 16384;
        uint32_t stV = stK + 8192;

        // ---- S = Q @ K^T (log2 domain) ----
        float S[8][4];
#pragma unroll
        for (int jt = 0; jt < 8; jt++)
#pragma unroll
            for (int c = 0; c < 4; c++) S[jt][c] = 0.f;

#pragma unroll
        for (int jp = 0; jp < 4; jp++) {
#pragma unroll
            for (int ks = 0; ks < 4; ks++) {
                uint32_t off = SMEM_SWIZZLE_128B((jp * 16 + bp_row) * 128 + ks * 32 + bp_cb);
                uint32_t r4[4];
                ldsm_x4(r4, stK + off);
                mma_f16(S[2 * jp],     qh[ks], r4);
                mma_f16(S[2 * jp + 1], qh[ks], r4 + 2);
            }
        }

        if (j >= 2 * qt) {
            int r0 = q0 + wid * 16 + g4;
            int cb = j * 64 + c2;
#pragma unroll
            for (int jt = 0; jt < 8; jt++) {
                int c0 = cb + jt * 8;
                if (c0 > r0)     S[jt][0] = -1e30f;
                if (c0 + 1 > r0) S[jt][1] = -1e30f;
                if (c0 > r0 + 8)     S[jt][2] = -1e30f;
                if (c0 + 1 > r0 + 8) S[jt][3] = -1e30f;
            }
        }

        float mx0 = -1e30f, mx1 = -1e30f;
#pragma unroll
        for (int jt = 0; jt < 8; jt++) {
            mx0 = fmaxf(mx0, fmaxf(S[jt][0], S[jt][1]));
            mx1 = fmaxf(mx1, fmaxf(S[jt][2], S[jt][3]));
        }
        mx0 = fmaxf(mx0, __shfl_xor_sync(0xffffffffu, mx0, 1));
        mx0 = fmaxf(mx0, __shfl_xor_sync(0xffffffffu, mx0, 2));
        mx1 = fmaxf(mx1, __shfl_xor_sync(0xffffffffu, mx1, 1));
        mx1 = fmaxf(mx1, __shfl_xor_sync(0xffffffffu, mx1, 2));

        float mn0 = fmaxf(m0r, mx0), mn1 = fmaxf(m1r, mx1);
        float al0 = ex2(m0r - mn0), al1 = ex2(m1r - mn1);
        m0r = mn0; m1r = mn1;

        float s0 = 0.f, s1 = 0.f;
#pragma unroll
        for (int jt = 0; jt < 8; jt++) {
            S[jt][0] = ex2(S[jt][0] - mn0); s0 += S[jt][0];
            S[jt][1] = ex2(S[jt][1] - mn0); s0 += S[jt][1];
            S[jt][2] = ex2(S[jt][2] - mn1); s1 += S[jt][2];
            S[jt][3] = ex2(S[jt][3] - mn1); s1 += S[jt][3];
        }
        s0 += __shfl_xor_sync(0xffffffffu, s0, 1);
        s0 += __shfl_xor_sync(0xffffffffu, s0, 2);
        s1 += __shfl_xor_sync(0xffffffffu, s1, 1);
        s1 += __shfl_xor_sync(0xffffffffu, s1, 2);
        l0r = l0r * al0 + s0;
        l1r = l1r * al1 + s1;

#pragma unroll
        for (int dt = 0; dt < 8; dt++) {
            O[dt][0] *= al0; O[dt][1] *= al0;
            O[dt][2] *= al1; O[dt][3] *= al1;
        }

        // ---- pack P (fp16) in place ----
#pragma unroll
        for (int ks2 = 0; ks2 < 4; ks2++) {
#pragma unroll
            for (int q = 0; q < 4; q++) {
                int tile = 2 * ks2 + (q >> 1);
                int cb = (q & 1) * 2;
                S[tile][cb] = __uint_as_float(pack_h2(S[tile][cb], S[tile][cb + 1]));
            }
        }

        // ---- O += P @ V ----
#pragma unroll
        for (int dtp = 0; dtp < 4; dtp++) {
#pragma unroll
            for (int ks2 = 0; ks2 < 4; ks2++) {
                uint32_t ph[4] = {
                    __float_as_uint(S[2 * ks2][0]),     __float_as_uint(S[2 * ks2][2]),
                    __float_as_uint(S[2 * ks2 + 1][0]), __float_as_uint(S[2 * ks2 + 1][2])};
                uint32_t off = SMEM_SWIZZLE_128B((ks2 * 16 + v_row) * 128 +
                                                 (2 * dtp + v_ct) * 16);
                uint32_t r4[4];
                ldsm_x4_trans(r4, stV + off);
                mma_f16(O[2 * dtp],     ph, r4);
                mma_f16(O[2 * dtp + 1], ph, r4 + 2);
            }
        }
        __syncthreads();
    }

    // ---- epilogue: y = O / l, fp16 ----
    float li0 = 1.f / l0r, li1 = 1.f / l1r;
    int b = bh >> 4, h = bh & 15;
    int r0 = q0 + wid * 16 + g4;
#pragma unroll
    for (int dt = 0; dt < 8; dt++) {
        int d = dt * 8 + c2;
        {
            size_t off = (size_t)(b * T_ + r0) * C_ + h * DH_ + d;
            *(uint32_t*)(g_yh + off) = pack_h2(O[dt][0] * li0, O[dt][1] * li0);
        }
        {
            size_t off = (size_t)(b * T_ + r0 + 8) * C_ + h * DH_ + d;
            *(uint32_t*)(g_yh + off) = pack_h2(O[dt][2] * li1, O[dt][3] * li1);
        }
    }
}

// ---------------------------------------------------------------------------
extern "C" void kernel_launch(void* const* d_in, const int* in_sizes, int n_in,
                              void* d_out, int out_size)
{
    const float* x      = (const float*)d_in[0];
    const float* w_qkv  = (const float*)d_in[1];
    const float* w_proj = (const float*)d_in[2];
    float* out = (float*)d_out;
    (void)in_sizes; (void)n_in; (void)out_size;

    cudaFuncSetAttribute(mma_gemm_kernel,
                         cudaFuncAttributeMaxDynamicSharedMemorySize, SM_GEMM_TOTAL);
    cudaFuncSetAttribute(attn_mma_kernel,
                         cudaFuncAttributeMaxDynamicSharedMemorySize, AS_TOTAL);

    __half *xh, *yh, *wq, *wp;
    cudaGetSymbolAddress((void**)&xh, g_xh);
    cudaGetSymbolAddress((void**)&yh, g_yh);
    cudaGetSymbolAddress((void**)&wq, g_wqkvT);
    cudaGetSymbolAddress((void**)&wp, g_wprojT);

    // fused prep
    prep_kernel<<<PREP_BLOCKS, 256>>>(x, w_qkv, w_proj);

    // QKV GEMM (1-term) with fused q-scale(+log2e) + scatter
    mma_gemm_kernel<<<dim3(N_QKV / 128, M_ / 128), 256, SM_GEMM_TOTAL>>>(
        xh, wq, nullptr, 0);

    // tensor-core causal flash attention (softmax in log2 domain)
    attn_mma_kernel<<<dim3(B_ * H_, T_ / 128), 256, AS_TOTAL>>>();

    // output projection GEMM (1-term)
    mma_gemm_kernel<<<dim3(C_ / 128, M_ / 128), 256, SM_GEMM_TOTAL>>>(
        yh, wp, out, 1);
}

// round 15
// speedup vs baseline: 1.5077x; 1.0018x over previous
#include <cuda_runtime.h>
#include <cuda_fp16.h>
#include <cstdint>
#include <cstring>

// Problem constants
#define B_   4
#define T_   2048
#define C_   1024
#define H_   16
#define DH_  64
#define M_   (B_ * T_)          // 8192
#define N_QKV (3 * C_)          // 3072
#define K_   1024

#define LOG2E 1.4426950408889634f

// ---------------------------------------------------------------------------
// Device-global scratch
// ---------------------------------------------------------------------------
__device__ __half g_qh[B_ * H_ * T_ * DH_];
__device__ __half g_kh[B_ * H_ * T_ * DH_];
__device__ __half g_vh[B_ * H_ * T_ * DH_];
__device__ __half g_xh[M_ * K_];
__device__ __half g_yh[M_ * C_];
__device__ __half g_wqkvT[N_QKV * K_];   // [N][K]
__device__ __half g_wprojT[C_ * K_];

#define SMEM_SWIZZLE_128B(o) ((o) ^ (((o) >> 3) & 0x70))

__device__ __forceinline__ uint32_t smem_to_u32(const void* p) {
    uint32_t a;
    asm("{ .reg .u64 t; cvta.to.shared.u64 t, %1; cvt.u32.u64 %0, t; }" : "=r"(a) : "l"(p));
    return a;
}
__device__ __forceinline__ void cp16(uint32_t saddr, const void* g) {
    asm volatile("cp.async.cg.shared.global [%0], [%1], 16;" :: "r"(saddr), "l"(g));
}
__device__ __forceinline__ void cp_commit() {
    asm volatile("cp.async.commit_group;" ::: "memory");
}
__device__ __forceinline__ void ldsm_x4(uint32_t* r, uint32_t addr) {
    asm volatile("ldmatrix.sync.aligned.m8n8.x4.shared.b16 {%0,%1,%2,%3}, [%4];"
        : "=r"(r[0]), "=r"(r[1]), "=r"(r[2]), "=r"(r[3]) : "r"(addr));
}
__device__ __forceinline__ void ldsm_x4_trans(uint32_t* r, uint32_t addr) {
    asm volatile("ldmatrix.sync.aligned.m8n8.x4.trans.shared.b16 {%0,%1,%2,%3}, [%4];"
        : "=r"(r[0]), "=r"(r[1]), "=r"(r[2]), "=r"(r[3]) : "r"(addr));
}
__device__ __forceinline__ void mma_f16(float* c, const uint32_t* a, const uint32_t* b) {
    asm volatile("mma.sync.aligned.m16n8k16.row.col.f32.f16.f16.f32 "
        "{%0,%1,%2,%3}, {%4,%5,%6,%7}, {%8,%9}, {%0,%1,%2,%3};"
        : "+f"(c[0]), "+f"(c[1]), "+f"(c[2]), "+f"(c[3])
        : "r"(a[0]), "r"(a[1]), "r"(a[2]), "r"(a[3]), "r"(b[0]), "r"(b[1]));
}
__device__ __forceinline__ uint32_t pack_h2(float lo, float hi) {
    __half2 h = __floats2half2_rn(lo, hi);
    uint32_t u; memcpy(&u, &h, 4); return u;
}
__device__ __forceinline__ float ex2(float x) {
    float r;
    asm("ex2.approx.ftz.f32 %0, %1;" : "=f"(r) : "f"(x));
    return r;
}
__device__ __forceinline__ uint32_t h2ex2(uint32_t x) {
    uint32_t r;
    asm("ex2.approx.f16x2 %0, %1;" : "=r"(r) : "r"(x));
    return r;
}
__device__ __forceinline__ float2 h2_to_f2(uint32_t u) {
    __half2 h; memcpy(&h, &u, 4);
    return __half22float2(h);
}

// ---------------------------------------------------------------------------
// Fused prep kernel (blockIdx-partitioned)
// ---------------------------------------------------------------------------
#define PREP_X_BLOCKS  (M_ * K_ / (256 * 4))          // 8192
#define PREP_WQ_BLOCKS ((N_QKV / 32) * (K_ / 32))     // 3072
#define PREP_WP_BLOCKS ((C_ / 32) * (K_ / 32))        // 1024
#define PREP_BLOCKS (PREP_X_BLOCKS + PREP_WQ_BLOCKS + PREP_WP_BLOCKS)

__global__ __launch_bounds__(256) void prep_kernel(
    const float* __restrict__ x,
    const float* __restrict__ wqkv,
    const float* __restrict__ wproj)
{
    __shared__ float t[32][33];
    int bid = blockIdx.x;
    int tid = threadIdx.x;

    if (bid < PREP_X_BLOCKS) {
        int idx = (bid * 256 + tid) * 4;
        float4 v = *(const float4*)(x + idx);
        float vv[4] = {v.x, v.y, v.z, v.w};
        __half h[4];
#pragma unroll
        for (int i = 0; i < 4; i++) h[i] = __float2half_rn(vv[i]);
        *(uint2*)(g_xh + idx) = *(uint2*)h;
        return;
    }

    const float* W;
    __half* WT;
    int N, bx, by;
    if (bid < PREP_X_BLOCKS + PREP_WQ_BLOCKS) {
        int b = bid - PREP_X_BLOCKS;
        W = wqkv; WT = g_wqkvT; N = N_QKV;
        bx = b % (N_QKV / 32); by = b / (N_QKV / 32);
    } else {
        int b = bid - PREP_X_BLOCKS - PREP_WQ_BLOCKS;
        W = wproj; WT = g_wprojT; N = C_;
        bx = b % (C_ / 32); by = b / (C_ / 32);
    }
    int n0 = bx * 32, k0 = by * 32;
    int tx = tid & 31, ty = tid >> 5;
#pragma unroll
    for (int i = 0; i < 4; i++)
        t[ty + i * 8][tx] = W[(size_t)(k0 + ty + i * 8) * N + n0 + tx];
    __syncthreads();
#pragma unroll
    for (int i = 0; i < 4; i++) {
        int n = n0 + ty + i * 8;
        int k = k0 + tx;
        WT[(size_t)n * K_ + k] = __float2half_rn(t[tx][ty + i * 8]);
    }
}

// ---------------------------------------------------------------------------
// Tensor-core GEMM — R12/R14 pipeline (2-stage, load-before-wait, 2 syncs).
// CTA tile 128x128, BK=64, 8 warps (2m x 4n), warp tile 64x32.
// mode 0: scatter q (scaled by 0.125*log2e) / k / v; mode 1: f32 store.
// ---------------------------------------------------------------------------
#define STAGE_BYTES 32768
#define SM_GEMM_TOTAL (2 * STAGE_BYTES)   // 65536

__global__ __launch_bounds__(256, 2) void mma_gemm_kernel(
    const __half* __restrict__ Ah, const __half* __restrict__ Bm,
    float* __restrict__ out, int mode)
{
    extern __shared__ char smem[];
    uint32_t sbase = smem_to_u32(smem);

    int tid = threadIdx.x;
    int wid = tid >> 5;
    int lane = tid & 31;
    int wm = wid >> 2;
    int wn = wid & 3;

    int m0 = blockIdx.y * 128;
    int n0 = blockIdx.x * 128;

    float acc[4][4][4];
#pragma unroll
    for (int i = 0; i < 4; i++)
#pragma unroll
        for (int j = 0; j < 4; j++)
#pragma unroll
            for (int c = 0; c < 4; c++) acc[i][j][c] = 0.f;

    auto load_chunk = [&](int kt, int s) {
        uint32_t st = sbase + s * STAGE_BYTES;
#pragma unroll
        for (int p = 0; p < 4; p++) {
            int idx = tid + p * 256;
            int row = idx >> 3;
            int ch  = idx & 7;
            uint32_t so = SMEM_SWIZZLE_128B(row * 128 + ch * 16);
            size_t ka = (size_t)(m0 + row) * K_ + kt * 64 + ch * 8;
            size_t kb = (size_t)(n0 + row) * K_ + kt * 64 + ch * 8;
            cp16(st + so,         Ah + ka);
            cp16(st + 16384 + so, Bm + kb);
        }
        cp_commit();
    };

    load_chunk(0, 0);

    int a_row = lane & 15;
    int a_cb  = (lane >> 4) << 4;
    int bg     = lane >> 3;
    int bp_row = (lane & 7) + ((bg >> 1) << 3);
    int bp_cb  = (bg & 1) << 4;

    for (int kt = 0; kt < 16; kt++) {
        int s = kt & 1;
        if (kt + 1 < 16) {
            load_chunk(kt + 1, (kt + 1) & 1);
            asm volatile("cp.async.wait_group 1;" ::: "memory");
        } else {
            asm volatile("cp.async.wait_group 0;" ::: "memory");
        }
        __syncthreads();

        uint32_t sA = sbase + s * STAGE_BYTES;
        uint32_t sB = sA + 16384;

#pragma unroll
        for (int ks = 0; ks < 4; ks++) {
            int kB = ks * 32;
            uint32_t ah[4][4], bh[4][2];
#pragma unroll
            for (int i = 0; i < 4; i++) {
                uint32_t off = SMEM_SWIZZLE_128B((wm * 64 + i * 16 + a_row) * 128 + kB + a_cb);
                ldsm_x4(ah[i], sA + off);
            }
#pragma unroll
            for (int jp = 0; jp < 2; jp++) {
                uint32_t off = SMEM_SWIZZLE_128B((wn * 32 + jp * 16 + bp_row) * 128 + kB + bp_cb);
                uint32_t r4[4];
                ldsm_x4(r4, sB + off);
                bh[2 * jp][0] = r4[0]; bh[2 * jp][1] = r4[1];
                bh[2 * jp + 1][0] = r4[2]; bh[2 * jp + 1][1] = r4[3];
            }
#pragma unroll
            for (int i = 0; i < 4; i++)
#pragma unroll
                for (int j = 0; j < 4; j++) mma_f16(acc[i][j], ah[i], bh[j]);
        }
        __syncthreads();
    }

    int r4i = lane >> 2;
    int cp2 = (lane & 3) * 2;

    if (mode == 1) {
#pragma unroll
        for (int i = 0; i < 4; i++)
#pragma unroll
            for (int j = 0; j < 4; j++) {
                int n = n0 + wn * 32 + j * 8 + cp2;
#pragma unroll
                for (int rr = 0; rr < 2; rr++) {
                    int m = m0 + wm * 64 + i * 16 + r4i + rr * 8;
                    *(float2*)(out + (size_t)m * C_ + n) =
                        make_float2(acc[i][j][rr * 2], acc[i][j][rr * 2 + 1]);
                }
            }
    } else {
        int which = n0 >> 10;
        __half* dst = (which == 0) ? g_qh : (which == 1) ? g_kh : g_vh;
        float scale = (which == 0) ? (0.125f * LOG2E) : 1.0f;
#pragma unroll
        for (int i = 0; i < 4; i++)
#pragma unroll
            for (int j = 0; j < 4; j++) {
                int n = n0 + wn * 32 + j * 8 + cp2;
                int h = (n & 1023) >> 6;
                int d = n & 63;
#pragma unroll
                for (int rr = 0; rr < 2; rr++) {
                    int m = m0 + wm * 64 + i * 16 + r4i + rr * 8;
                    int b = m >> 11;
                    int t = m & 2047;
                    size_t off = (size_t)(((b << 4) + h) * T_ + t) * DH_ + d;
                    *(uint32_t*)(dst + off) =
                        pack_h2(acc[i][j][rr * 2] * scale, acc[i][j][rr * 2 + 1] * scale);
                }
            }
    }
}

// ---------------------------------------------------------------------------
// Tensor-core causal flash attention — R14 pipeline; softmax exp in f16x2
// (halves MUFU, output IS the packed fp16 P fragment; l-sum stays fp32).
// Smem: Q(16K) + 2 x (K8|V8) = 48K -> 2 CTAs/SM. LPT grid.
// ---------------------------------------------------------------------------
#define AS_Q  0
#define AS_KV 16384
#define AS_TOTAL (16384 + 2 * 16384)   // 49152

__global__ __launch_bounds__(256, 2) void attn_mma_kernel()
{
    extern __shared__ char smem[];
    uint32_t sb = smem_to_u32(smem);
    int tid = threadIdx.x;
    int wid = tid >> 5;
    int lane = tid & 31;

    int qt = 15 - blockIdx.y;     // longest first
    int bh = blockIdx.x;
    int q0 = qt * 128;
    size_t base = (size_t)bh * T_ * DH_;
    int nkt = 2 * qt + 2;

#pragma unroll
    for (int p = 0; p < 4; p++) {
        int idx = tid + p * 256;
        int row = idx >> 3;
        int ch  = idx & 7;
        uint32_t so = SMEM_SWIZZLE_128B(row * 128 + ch * 16);
        cp16(sb + AS_Q + so, g_qh + base + (size_t)(q0 + row) * DH_ + ch * 8);
    }
    cp_commit();

    auto load_kv = [&](int j, int s) {
        uint32_t st = sb + AS_KV + s * 16384;
#pragma unroll
        for (int p = 0; p < 2; p++) {
            int idx = tid + p * 256;
            int row = idx >> 3;
            int ch  = idx & 7;
            uint32_t so = SMEM_SWIZZLE_128B(row * 128 + ch * 16);
            size_t g = base + (size_t)(j * 64 + row) * DH_ + ch * 8;
            cp16(st + so,        g_kh + g);
            cp16(st + 8192 + so, g_vh + g);
        }
        cp_commit();
    };

    load_kv(0, 0);

    uint32_t qh[4][4];
    float O[8][4];
#pragma unroll
    for (int dt = 0; dt < 8; dt++)
#pragma unroll
        for (int c = 0; c < 4; c++) O[dt][c] = 0.f;
    float m0r = -1e30f, m1r = -1e30f, l0r = 0.f, l1r = 0.f;

    int g4 = lane >> 2;
    int c2 = 2 * (lane & 3);
    int a_row = lane & 15;
    int a_cb  = (lane >> 4) << 4;
    int bg     = lane >> 3;
    int bp_row = (lane & 7) + ((bg >> 1) << 3);
    int bp_cb  = (bg & 1) << 4;
    int v_row = (lane & 7) + ((lane >> 3) & 1) * 8;
    int v_ct  = (lane >> 4) & 1;

    for (int j = 0; j < nkt; j++) {
        int s = j & 1;
        if (j + 1 < nkt) {
            load_kv(j + 1, (j + 1) & 1);
            asm volatile("cp.async.wait_group 1;" ::: "memory");
        } else {
            asm volatile("cp.async.wait_group 0;" ::: "memory");
        }
        __syncthreads();

        if (j == 0) {
#pragma unroll
            for (int ks = 0; ks < 4; ks++) {
                uint32_t off = SMEM_SWIZZLE_128B((wid * 16 + a_row) * 128 + ks * 32 + a_cb);
                ldsm_x4(qh[ks], sb + AS_Q + off);
            }
        }

        uint32_t stK = sb + AS_KV + s * 16384;
        uint32_t stV = stK + 8192;

        // ---- S = Q @ K^T (log2 domain) ----
        float S[8][4];
#pragma unroll
        for (int jt = 0; jt < 8; jt++)
#pragma unroll
            for (int c = 0; c < 4; c++) S[jt][c] = 0.f;

#pragma unroll
        for (int jp = 0; jp < 4; jp++) {
#pragma unroll
            for (int ks = 0; ks < 4; ks++) {
                uint32_t off = SMEM_SWIZZLE_128B((jp * 16 + bp_row) * 128 + ks * 32 + bp_cb);
                uint32_t r4[4];
                ldsm_x4(r4, stK + off);
                mma_f16(S[2 * jp],     qh[ks], r4);
                mma_f16(S[2 * jp + 1], qh[ks], r4 + 2);
            }
        }

        if (j >= 2 * qt) {
            int r0 = q0 + wid * 16 + g4;
            int cb = j * 64 + c2;
#pragma unroll
            for (int jt = 0; jt < 8; jt++) {
                int c0 = cb + jt * 8;
                if (c0 > r0)     S[jt][0] = -1e30f;
                if (c0 + 1 > r0) S[jt][1] = -1e30f;
                if (c0 > r0 + 8)     S[jt][2] = -1e30f;
                if (c0 + 1 > r0 + 8) S[jt][3] = -1e30f;
            }
        }

        float mx0 = -1e30f, mx1 = -1e30f;
#pragma unroll
        for (int jt = 0; jt < 8; jt++) {
            mx0 = fmaxf(mx0, fmaxf(S[jt][0], S[jt][1]));
            mx1 = fmaxf(mx1, fmaxf(S[jt][2], S[jt][3]));
        }
        mx0 = fmaxf(mx0, __shfl_xor_sync(0xffffffffu, mx0, 1));
        mx0 = fmaxf(mx0, __shfl_xor_sync(0xffffffffu, mx0, 2));
        mx1 = fmaxf(mx1, __shfl_xor_sync(0xffffffffu, mx1, 1));
        mx1 = fmaxf(mx1, __shfl_xor_sync(0xffffffffu, mx1, 2));

        float mn0 = fmaxf(m0r, mx0), mn1 = fmaxf(m1r, mx1);
        float al0 = ex2(m0r - mn0), al1 = ex2(m1r - mn1);
        m0r = mn0; m1r = mn1;

        // ---- exp in f16x2: result is the packed P fragment directly ----
        float s0 = 0.f, s1 = 0.f;
#pragma unroll
        for (int jt = 0; jt < 8; jt++) {
            uint32_t p0 = h2ex2(pack_h2(S[jt][0] - mn0, S[jt][1] - mn0));
            uint32_t p1 = h2ex2(pack_h2(S[jt][2] - mn1, S[jt][3] - mn1));
            float2 f0 = h2_to_f2(p0);
            float2 f1 = h2_to_f2(p1);
            s0 += f0.x + f0.y;
            s1 += f1.x + f1.y;
            S[jt][0] = __uint_as_float(p0);   // packed P rows (r)
            S[jt][2] = __uint_as_float(p1);   // packed P rows (r+8)
        }
        s0 += __shfl_xor_sync(0xffffffffu, s0, 1);
        s0 += __shfl_xor_sync(0xffffffffu, s0, 2);
        s1 += __shfl_xor_sync(0xffffffffu, s1, 1);
        s1 += __shfl_xor_sync(0xffffffffu, s1, 2);
        l0r = l0r * al0 + s0;
        l1r = l1r * al1 + s1;

#pragma unroll
        for (int dt = 0; dt < 8; dt++) {
            O[dt][0] *= al0; O[dt][1] *= al0;
            O[dt][2] *= al1; O[dt][3] *= al1;
        }

        // ---- O += P @ V ----
#pragma unroll
        for (int dtp = 0; dtp < 4; dtp++) {
#pragma unroll
            for (int ks2 = 0; ks2 < 4; ks2++) {
                uint32_t ph[4] = {
                    __float_as_uint(S[2 * ks2][0]),     __float_as_uint(S[2 * ks2][2]),
                    __float_as_uint(S[2 * ks2 + 1][0]), __float_as_uint(S[2 * ks2 + 1][2])};
                uint32_t off = SMEM_SWIZZLE_128B((ks2 * 16 + v_row) * 128 +
                                                 (2 * dtp + v_ct) * 16);
                uint32_t r4[4];
                ldsm_x4_trans(r4, stV + off);
                mma_f16(O[2 * dtp],     ph, r4);
                mma_f16(O[2 * dtp + 1], ph, r4 + 2);
            }
        }
        __syncthreads();
    }

    // ---- epilogue: y = O / l, fp16 ----
    float li0 = 1.f / l0r, li1 = 1.f / l1r;
    int b = bh >> 4, h = bh & 15;
    int r0 = q0 + wid * 16 + g4;
#pragma unroll
    for (int dt = 0; dt < 8; dt++) {
        int d = dt * 8 + c2;
        {
            size_t off = (size_t)(b * T_ + r0) * C_ + h * DH_ + d;
            *(uint32_t*)(g_yh + off) = pack_h2(O[dt][0] * li0, O[dt][1] * li0);
        }
        {
            size_t off = (size_t)(b * T_ + r0 + 8) * C_ + h * DH_ + d;
            *(uint32_t*)(g_yh + off) = pack_h2(O[dt][2] * li1, O[dt][3] * li1);
        }
    }
}

// ---------------------------------------------------------------------------
extern "C" void kernel_launch(void* const* d_in, const int* in_sizes, int n_in,
                              void* d_out, int out_size)
{
    const float* x      = (const float*)d_in[0];
    const float* w_qkv  = (const float*)d_in[1];
    const float* w_proj = (const float*)d_in[2];
    float* out = (float*)d_out;
    (void)in_sizes; (void)n_in; (void)out_size;

    cudaFuncSetAttribute(mma_gemm_kernel,
                         cudaFuncAttributeMaxDynamicSharedMemorySize, SM_GEMM_TOTAL);
    cudaFuncSetAttribute(attn_mma_kernel,
                         cudaFuncAttributeMaxDynamicSharedMemorySize, AS_TOTAL);

    __half *xh, *yh, *wq, *wp;
    cudaGetSymbolAddress((void**)&xh, g_xh);
    cudaGetSymbolAddress((void**)&yh, g_yh);
    cudaGetSymbolAddress((void**)&wq, g_wqkvT);
    cudaGetSymbolAddress((void**)&wp, g_wprojT);

    // fused prep
    prep_kernel<<<PREP_BLOCKS, 256>>>(x, w_qkv, w_proj);

    // QKV GEMM (1-term) with fused q-scale(+log2e) + scatter
    mma_gemm_kernel<<<dim3(N_QKV / 128, M_ / 128), 256, SM_GEMM_TOTAL>>>(
        xh, wq, nullptr, 0);

    // tensor-core causal flash attention (f16x2 softmax)
    attn_mma_kernel<<<dim3(B_ * H_, T_ / 128), 256, AS_TOTAL>>>();

    // output projection GEMM (1-term)
    mma_gemm_kernel<<<dim3(C_ / 128, M_ / 128), 256, SM_GEMM_TOTAL>>>(
        yh, wp, out, 1);
}

// round 16
// speedup vs baseline: 1.5448x; 1.0246x over previous
#include <cuda_runtime.h>
#include <cuda_fp16.h>
#include <cstdint>
#include <cstring>

// Problem constants
#define B_   4
#define T_   2048
#define C_   1024
#define H_   16
#define DH_  64
#define M_   (B_ * T_)          // 8192
#define N_QKV (3 * C_)          // 3072
#define K_   1024

#define LOG2E 1.4426950408889634f

// ---------------------------------------------------------------------------
// Device-global scratch
// ---------------------------------------------------------------------------
__device__ __half g_qh[B_ * H_ * T_ * DH_];
__device__ __half g_kh[B_ * H_ * T_ * DH_];
__device__ __half g_vh[B_ * H_ * T_ * DH_];
__device__ __half g_xh[M_ * K_];
__device__ __half g_yh[M_ * C_];
__device__ __half g_wqkvT[N_QKV * K_];   // [N][K]
__device__ __half g_wprojT[C_ * K_];

#define SMEM_SWIZZLE_128B(o) ((o) ^ (((o) >> 3) & 0x70))

__device__ __forceinline__ uint32_t smem_to_u32(const void* p) {
    uint32_t a;
    asm("{ .reg .u64 t; cvta.to.shared.u64 t, %1; cvt.u32.u64 %0, t; }" : "=r"(a) : "l"(p));
    return a;
}
__device__ __forceinline__ void cp16(uint32_t saddr, const void* g) {
    asm volatile("cp.async.cg.shared.global [%0], [%1], 16;" :: "r"(saddr), "l"(g));
}
__device__ __forceinline__ void cp_commit() {
    asm volatile("cp.async.commit_group;" ::: "memory");
}
__device__ __forceinline__ void ldsm_x4(uint32_t* r, uint32_t addr) {
    asm volatile("ldmatrix.sync.aligned.m8n8.x4.shared.b16 {%0,%1,%2,%3}, [%4];"
        : "=r"(r[0]), "=r"(r[1]), "=r"(r[2]), "=r"(r[3]) : "r"(addr));
}
__device__ __forceinline__ void ldsm_x4_trans(uint32_t* r, uint32_t addr) {
    asm volatile("ldmatrix.sync.aligned.m8n8.x4.trans.shared.b16 {%0,%1,%2,%3}, [%4];"
        : "=r"(r[0]), "=r"(r[1]), "=r"(r[2]), "=r"(r[3]) : "r"(addr));
}
__device__ __forceinline__ void mma_f16(float* c, const uint32_t* a, const uint32_t* b) {
    asm volatile("mma.sync.aligned.m16n8k16.row.col.f32.f16.f16.f32 "
        "{%0,%1,%2,%3}, {%4,%5,%6,%7}, {%8,%9}, {%0,%1,%2,%3};"
        : "+f"(c[0]), "+f"(c[1]), "+f"(c[2]), "+f"(c[3])
        : "r"(a[0]), "r"(a[1]), "r"(a[2]), "r"(a[3]), "r"(b[0]), "r"(b[1]));
}
__device__ __forceinline__ uint32_t pack_h2(float lo, float hi) {
    __half2 h = __floats2half2_rn(lo, hi);
    uint32_t u; memcpy(&u, &h, 4); return u;
}
__device__ __forceinline__ float ex2(float x) {
    float r;
    asm("ex2.approx.ftz.f32 %0, %1;" : "=f"(r) : "f"(x));
    return r;
}
__device__ __forceinline__ uint32_t h2ex2(uint32_t x) {
    uint32_t r;
    asm("ex2.approx.f16x2 %0, %1;" : "=r"(r) : "r"(x));
    return r;
}
__device__ __forceinline__ float2 h2_to_f2(uint32_t u) {
    __half2 h; memcpy(&h, &u, 4);
    return __half22float2(h);
}

// ---------------------------------------------------------------------------
// Fused prep kernel (blockIdx-partitioned)
// ---------------------------------------------------------------------------
#define PREP_X_BLOCKS  (M_ * K_ / (256 * 4))          // 8192
#define PREP_WQ_BLOCKS ((N_QKV / 32) * (K_ / 32))     // 3072
#define PREP_WP_BLOCKS ((C_ / 32) * (K_ / 32))        // 1024
#define PREP_BLOCKS (PREP_X_BLOCKS + PREP_WQ_BLOCKS + PREP_WP_BLOCKS)

__global__ __launch_bounds__(256) void prep_kernel(
    const float* __restrict__ x,
    const float* __restrict__ wqkv,
    const float* __restrict__ wproj)
{
    __shared__ float t[32][33];
    int bid = blockIdx.x;
    int tid = threadIdx.x;

    if (bid < PREP_X_BLOCKS) {
        int idx = (bid * 256 + tid) * 4;
        float4 v = *(const float4*)(x + idx);
        float vv[4] = {v.x, v.y, v.z, v.w};
        __half h[4];
#pragma unroll
        for (int i = 0; i < 4; i++) h[i] = __float2half_rn(vv[i]);
        *(uint2*)(g_xh + idx) = *(uint2*)h;
        return;
    }

    const float* W;
    __half* WT;
    int N, bx, by;
    if (bid < PREP_X_BLOCKS + PREP_WQ_BLOCKS) {
        int b = bid - PREP_X_BLOCKS;
        W = wqkv; WT = g_wqkvT; N = N_QKV;
        bx = b % (N_QKV / 32); by = b / (N_QKV / 32);
    } else {
        int b = bid - PREP_X_BLOCKS - PREP_WQ_BLOCKS;
        W = wproj; WT = g_wprojT; N = C_;
        bx = b % (C_ / 32); by = b / (C_ / 32);
    }
    int n0 = bx * 32, k0 = by * 32;
    int tx = tid & 31, ty = tid >> 5;
#pragma unroll
    for (int i = 0; i < 4; i++)
        t[ty + i * 8][tx] = W[(size_t)(k0 + ty + i * 8) * N + n0 + tx];
    __syncthreads();
#pragma unroll
    for (int i = 0; i < 4; i++) {
        int n = n0 + ty + i * 8;
        int k = k0 + tx;
        WT[(size_t)n * K_ + k] = __float2half_rn(t[tx][ty + i * 8]);
    }
}

// ---------------------------------------------------------------------------
// Tensor-core GEMM — R12 pipeline, templated on AI (m-tiles per warp).
// BM = 32*AI (AI=4: 128x128 CTA tile; AI=2: 64x128). BN=128, BK=64,
// 8 warps (2m x 4n). Stage = BM*128 + 16K, double-buffered -> 2 CTAs/SM.
// mode 0: scatter q (scaled by 0.125*log2e) / k / v; mode 1: f32 store.
// ---------------------------------------------------------------------------
template<int AI>
__global__ __launch_bounds__(256, 2) void mma_gemm_kernel(
    const __half* __restrict__ Ah, const __half* __restrict__ Bm,
    float* __restrict__ out, int mode)
{
    constexpr int BM = 32 * AI;
    constexpr int A_STAGE = BM * 128;
    constexpr int STAGE = A_STAGE + 16384;

    extern __shared__ char smem[];
    uint32_t sbase = smem_to_u32(smem);

    int tid = threadIdx.x;
    int wid = tid >> 5;
    int lane = tid & 31;
    int wm = wid >> 2;
    int wn = wid & 3;

    int m0 = blockIdx.y * BM;
    int n0 = blockIdx.x * 128;

    float acc[AI][4][4];
#pragma unroll
    for (int i = 0; i < AI; i++)
#pragma unroll
        for (int j = 0; j < 4; j++)
#pragma unroll
            for (int c = 0; c < 4; c++) acc[i][j][c] = 0.f;

    auto load_chunk = [&](int kt, int s) {
        uint32_t st = sbase + s * STAGE;
#pragma unroll
        for (int p = 0; p < AI; p++) {
            int idx = tid + p * 256;
            int row = idx >> 3;
            int ch  = idx & 7;
            uint32_t so = SMEM_SWIZZLE_128B(row * 128 + ch * 16);
            size_t ka = (size_t)(m0 + row) * K_ + kt * 64 + ch * 8;
            cp16(st + so, Ah + ka);
        }
#pragma unroll
        for (int p = 0; p < 4; p++) {
            int idx = tid + p * 256;
            int row = idx >> 3;
            int ch  = idx & 7;
            uint32_t so = SMEM_SWIZZLE_128B(row * 128 + ch * 16);
            size_t kb = (size_t)(n0 + row) * K_ + kt * 64 + ch * 8;
            cp16(st + A_STAGE + so, Bm + kb);
        }
        cp_commit();
    };

    load_chunk(0, 0);

    int a_row = lane & 15;
    int a_cb  = (lane >> 4) << 4;
    int bg     = lane >> 3;
    int bp_row = (lane & 7) + ((bg >> 1) << 3);
    int bp_cb  = (bg & 1) << 4;

    for (int kt = 0; kt < 16; kt++) {
        int s = kt & 1;
        if (kt + 1 < 16) {
            load_chunk(kt + 1, (kt + 1) & 1);
            asm volatile("cp.async.wait_group 1;" ::: "memory");
        } else {
            asm volatile("cp.async.wait_group 0;" ::: "memory");
        }
        __syncthreads();

        uint32_t sA = sbase + s * STAGE;
        uint32_t sB = sA + A_STAGE;

#pragma unroll
        for (int ks = 0; ks < 4; ks++) {
            int kB = ks * 32;
            uint32_t ah[AI][4], bh[4][2];
#pragma unroll
            for (int i = 0; i < AI; i++) {
                uint32_t off = SMEM_SWIZZLE_128B((wm * (16 * AI) + i * 16 + a_row) * 128 + kB + a_cb);
                ldsm_x4(ah[i], sA + off);
            }
#pragma unroll
            for (int jp = 0; jp < 2; jp++) {
                uint32_t off = SMEM_SWIZZLE_128B((wn * 32 + jp * 16 + bp_row) * 128 + kB + bp_cb);
                uint32_t r4[4];
                ldsm_x4(r4, sB + off);
                bh[2 * jp][0] = r4[0]; bh[2 * jp][1] = r4[1];
                bh[2 * jp + 1][0] = r4[2]; bh[2 * jp + 1][1] = r4[3];
            }
#pragma unroll
            for (int i = 0; i < AI; i++)
#pragma unroll
                for (int j = 0; j < 4; j++) mma_f16(acc[i][j], ah[i], bh[j]);
        }
        __syncthreads();
    }

    int r4i = lane >> 2;
    int cp2 = (lane & 3) * 2;

    if (mode == 1) {
#pragma unroll
        for (int i = 0; i < AI; i++)
#pragma unroll
            for (int j = 0; j < 4; j++) {
                int n = n0 + wn * 32 + j * 8 + cp2;
#pragma unroll
                for (int rr = 0; rr < 2; rr++) {
                    int m = m0 + wm * (16 * AI) + i * 16 + r4i + rr * 8;
                    *(float2*)(out + (size_t)m * C_ + n) =
                        make_float2(acc[i][j][rr * 2], acc[i][j][rr * 2 + 1]);
                }
            }
    } else {
        int which = n0 >> 10;
        __half* dst = (which == 0) ? g_qh : (which == 1) ? g_kh : g_vh;
        float scale = (which == 0) ? (0.125f * LOG2E) : 1.0f;
#pragma unroll
        for (int i = 0; i < AI; i++)
#pragma unroll
            for (int j = 0; j < 4; j++) {
                int n = n0 + wn * 32 + j * 8 + cp2;
                int h = (n & 1023) >> 6;
                int d = n & 63;
#pragma unroll
                for (int rr = 0; rr < 2; rr++) {
                    int m = m0 + wm * (16 * AI) + i * 16 + r4i + rr * 8;
                    int b = m >> 11;
                    int t = m & 2047;
                    size_t off = (size_t)(((b << 4) + h) * T_ + t) * DH_ + d;
                    *(uint32_t*)(dst + off) =
                        pack_h2(acc[i][j][rr * 2] * scale, acc[i][j][rr * 2 + 1] * scale);
                }
            }
    }
}

// ---------------------------------------------------------------------------
// Tensor-core causal flash attention — KV tile 128 (two 64-halves per
// load+barrier), f16x2 softmax, log2 domain. R12 pipeline discipline.
// Smem: Q(16K) + 2 x (K16|V16) = 80K -> 2 CTAs/SM. LPT grid.
// ---------------------------------------------------------------------------
#define AS_Q  0
#define AS_KV 16384
#define KV_STAGE 32768        // K(16K) | V(16K)
#define AS_TOTAL (16384 + 2 * KV_STAGE)   // 81920

__global__ __launch_bounds__(256, 2) void attn_mma_kernel()
{
    extern __shared__ char smem[];
    uint32_t sb = smem_to_u32(smem);
    int tid = threadIdx.x;
    int wid = tid >> 5;
    int lane = tid & 31;

    int qt = 15 - blockIdx.y;     // longest first
    int bh = blockIdx.x;
    int q0 = qt * 128;
    size_t base = (size_t)bh * T_ * DH_;
    int njo = qt + 1;             // outer 128-kv tiles

#pragma unroll
    for (int p = 0; p < 4; p++) {
        int idx = tid + p * 256;
        int row = idx >> 3;
        int ch  = idx & 7;
        uint32_t so = SMEM_SWIZZLE_128B(row * 128 + ch * 16);
        cp16(sb + AS_Q + so, g_qh + base + (size_t)(q0 + row) * DH_ + ch * 8);
    }
    cp_commit();

    auto load_kv = [&](int jo, int s) {
        uint32_t st = sb + AS_KV + s * KV_STAGE;
#pragma unroll
        for (int p = 0; p < 4; p++) {
            int idx = tid + p * 256;          // 0..1023 -> 128 rows
            int row = idx >> 3;
            int ch  = idx & 7;
            uint32_t so = SMEM_SWIZZLE_128B(row * 128 + ch * 16);
            size_t g = base + (size_t)(jo * 128 + row) * DH_ + ch * 8;
            cp16(st + so,         g_kh + g);
            cp16(st + 16384 + so, g_vh + g);
        }
        cp_commit();
    };

    load_kv(0, 0);

    uint32_t qh[4][4];
    float O[8][4];
#pragma unroll
    for (int dt = 0; dt < 8; dt++)
#pragma unroll
        for (int c = 0; c < 4; c++) O[dt][c] = 0.f;
    float m0r = -1e30f, m1r = -1e30f, l0r = 0.f, l1r = 0.f;

    int g4 = lane >> 2;
    int c2 = 2 * (lane & 3);
    int a_row = lane & 15;
    int a_cb  = (lane >> 4) << 4;
    int bg     = lane >> 3;
    int bp_row = (lane & 7) + ((bg >> 1) << 3);
    int bp_cb  = (bg & 1) << 4;
    int v_row = (lane & 7) + ((lane >> 3) & 1) * 8;
    int v_ct  = (lane >> 4) & 1;

    for (int jo = 0; jo < njo; jo++) {
        int s = jo & 1;
        if (jo + 1 < njo) {
            load_kv(jo + 1, (jo + 1) & 1);
            asm volatile("cp.async.wait_group 1;" ::: "memory");
        } else {
            asm volatile("cp.async.wait_group 0;" ::: "memory");
        }
        __syncthreads();

        if (jo == 0) {
#pragma unroll
            for (int ks = 0; ks < 4; ks++) {
                uint32_t off = SMEM_SWIZZLE_128B((wid * 16 + a_row) * 128 + ks * 32 + a_cb);
                ldsm_x4(qh[ks], sb + AS_Q + off);
            }
        }

        uint32_t stK = sb + AS_KV + s * KV_STAGE;
        uint32_t stV = stK + 16384;

#pragma unroll
        for (int half = 0; half < 2; half++) {
            int j = 2 * jo + half;            // 64-kv index for masking
            int hrow = half * 64;

            // ---- S = Q @ K^T (log2 domain) ----
            float S[8][4];
#pragma unroll
            for (int jt = 0; jt < 8; jt++)
#pragma unroll
                for (int c = 0; c < 4; c++) S[jt][c] = 0.f;

#pragma unroll
            for (int jp = 0; jp < 4; jp++) {
#pragma unroll
                for (int ks = 0; ks < 4; ks++) {
                    uint32_t off = SMEM_SWIZZLE_128B((hrow + jp * 16 + bp_row) * 128 + ks * 32 + bp_cb);
                    uint32_t r4[4];
                    ldsm_x4(r4, stK + off);
                    mma_f16(S[2 * jp],     qh[ks], r4);
                    mma_f16(S[2 * jp + 1], qh[ks], r4 + 2);
                }
            }

            if (j >= 2 * qt) {
                int r0 = q0 + wid * 16 + g4;
                int cb = j * 64 + c2;
#pragma unroll
                for (int jt = 0; jt < 8; jt++) {
                    int c0 = cb + jt * 8;
                    if (c0 > r0)     S[jt][0] = -1e30f;
                    if (c0 + 1 > r0) S[jt][1] = -1e30f;
                    if (c0 > r0 + 8)     S[jt][2] = -1e30f;
                    if (c0 + 1 > r0 + 8) S[jt][3] = -1e30f;
                }
            }

            float mx0 = -1e30f, mx1 = -1e30f;
#pragma unroll
            for (int jt = 0; jt < 8; jt++) {
                mx0 = fmaxf(mx0, fmaxf(S[jt][0], S[jt][1]));
                mx1 = fmaxf(mx1, fmaxf(S[jt][2], S[jt][3]));
            }
            mx0 = fmaxf(mx0, __shfl_xor_sync(0xffffffffu, mx0, 1));
            mx0 = fmaxf(mx0, __shfl_xor_sync(0xffffffffu, mx0, 2));
            mx1 = fmaxf(mx1, __shfl_xor_sync(0xffffffffu, mx1, 1));
            mx1 = fmaxf(mx1, __shfl_xor_sync(0xffffffffu, mx1, 2));

            float mn0 = fmaxf(m0r, mx0), mn1 = fmaxf(m1r, mx1);
            float al0 = ex2(m0r - mn0), al1 = ex2(m1r - mn1);
            m0r = mn0; m1r = mn1;

            // ---- exp in f16x2: result IS the packed P fragment ----
            float s0 = 0.f, s1 = 0.f;
#pragma unroll
            for (int jt = 0; jt < 8; jt++) {
                uint32_t p0 = h2ex2(pack_h2(S[jt][0] - mn0, S[jt][1] - mn0));
                uint32_t p1 = h2ex2(pack_h2(S[jt][2] - mn1, S[jt][3] - mn1));
                float2 f0 = h2_to_f2(p0);
                float2 f1 = h2_to_f2(p1);
                s0 += f0.x + f0.y;
                s1 += f1.x + f1.y;
                S[jt][0] = __uint_as_float(p0);
                S[jt][2] = __uint_as_float(p1);
            }
            s0 += __shfl_xor_sync(0xffffffffu, s0, 1);
            s0 += __shfl_xor_sync(0xffffffffu, s0, 2);
            s1 += __shfl_xor_sync(0xffffffffu, s1, 1);
            s1 += __shfl_xor_sync(0xffffffffu, s1, 2);
            l0r = l0r * al0 + s0;
            l1r = l1r * al1 + s1;

#pragma unroll
            for (int dt = 0; dt < 8; dt++) {
                O[dt][0] *= al0; O[dt][1] *= al0;
                O[dt][2] *= al1; O[dt][3] *= al1;
            }

            // ---- O += P @ V ----
#pragma unroll
            for (int dtp = 0; dtp < 4; dtp++) {
#pragma unroll
                for (int ks2 = 0; ks2 < 4; ks2++) {
                    uint32_t ph[4] = {
                        __float_as_uint(S[2 * ks2][0]),     __float_as_uint(S[2 * ks2][2]),
                        __float_as_uint(S[2 * ks2 + 1][0]), __float_as_uint(S[2 * ks2 + 1][2])};
                    uint32_t off = SMEM_SWIZZLE_128B((hrow + ks2 * 16 + v_row) * 128 +
                                                     (2 * dtp + v_ct) * 16);
                    uint32_t r4[4];
                    ldsm_x4_trans(r4, stV + off);
                    mma_f16(O[2 * dtp],     ph, r4);
                    mma_f16(O[2 * dtp + 1], ph, r4 + 2);
                }
            }
        }
        __syncthreads();
    }

    // ---- epilogue: y = O / l, fp16 ----
    float li0 = 1.f / l0r, li1 = 1.f / l1r;
    int b = bh >> 4, h = bh & 15;
    int r0 = q0 + wid * 16 + g4;
#pragma unroll
    for (int dt = 0; dt < 8; dt++) {
        int d = dt * 8 + c2;
        {
            size_t off = (size_t)(b * T_ + r0) * C_ + h * DH_ + d;
            *(uint32_t*)(g_yh + off) = pack_h2(O[dt][0] * li0, O[dt][1] * li0);
        }
        {
            size_t off = (size_t)(b * T_ + r0 + 8) * C_ + h * DH_ + d;
            *(uint32_t*)(g_yh + off) = pack_h2(O[dt][2] * li1, O[dt][3] * li1);
        }
    }
}

// ---------------------------------------------------------------------------
extern "C" void kernel_launch(void* const* d_in, const int* in_sizes, int n_in,
                              void* d_out, int out_size)
{
    const float* x      = (const float*)d_in[0];
    const float* w_qkv  = (const float*)d_in[1];
    const float* w_proj = (const float*)d_in[2];
    float* out = (float*)d_out;
    (void)in_sizes; (void)n_in; (void)out_size;

    const int gemm4_smem = 2 * (128 * 128 + 16384);   // 65536
    const int gemm2_smem = 2 * (64 * 128 + 16384);    // 49152
    cudaFuncSetAttribute(mma_gemm_kernel<4>,
                         cudaFuncAttributeMaxDynamicSharedMemorySize, gemm4_smem);
    cudaFuncSetAttribute(mma_gemm_kernel<2>,
                         cudaFuncAttributeMaxDynamicSharedMemorySize, gemm2_smem);
    cudaFuncSetAttribute(attn_mma_kernel,
                         cudaFuncAttributeMaxDynamicSharedMemorySize, AS_TOTAL);

    __half *xh, *yh, *wq, *wp;
    cudaGetSymbolAddress((void**)&xh, g_xh);
    cudaGetSymbolAddress((void**)&yh, g_yh);
    cudaGetSymbolAddress((void**)&wq, g_wqkvT);
    cudaGetSymbolAddress((void**)&wp, g_wprojT);

    // fused prep
    prep_kernel<<<PREP_BLOCKS, 256>>>(x, w_qkv, w_proj);

    // QKV GEMM (128x128 tiles) with fused q-scale(+log2e) + scatter
    mma_gemm_kernel<4><<<dim3(N_QKV / 128, M_ / 128), 256, gemm4_smem>>>(
        xh, wq, nullptr, 0);

    // tensor-core causal flash attention (KV tile 128)
    attn_mma_kernel<<<dim3(B_ * H_, T_ / 128), 256, AS_TOTAL>>>();

    // output projection GEMM (64x128 tiles -> better wave quantization)
    mma_gemm_kernel<2><<<dim3(C_ / 128, M_ / 64), 256, gemm2_smem>>>(
        yh, wp, out, 1);
}

// round 17
// speedup vs baseline: 1.5668x; 1.0143x over previous
#include <cuda_runtime.h>
#include <cuda_fp16.h>
#include <cstdint>
#include <cstring>

// Problem constants
#define B_   4
#define T_   2048
#define C_   1024
#define H_   16
#define DH_  64
#define M_   (B_ * T_)          // 8192
#define N_QKV (3 * C_)          // 3072
#define K_   1024

#define LOG2E 1.4426950408889634f

// ---------------------------------------------------------------------------
// Device-global scratch
// ---------------------------------------------------------------------------
__device__ __half g_qh[B_ * H_ * T_ * DH_];
__device__ __half g_kh[B_ * H_ * T_ * DH_];
__device__ __half g_vh[B_ * H_ * T_ * DH_];
__device__ __half g_xh[M_ * K_];
__device__ __half g_yh[M_ * C_];
__device__ __half g_wqkvT[N_QKV * K_];   // [N][K]
__device__ __half g_wprojT[C_ * K_];

#define SMEM_SWIZZLE_128B(o) ((o) ^ (((o) >> 3) & 0x70))

__device__ __forceinline__ uint32_t smem_to_u32(const void* p) {
    uint32_t a;
    asm("{ .reg .u64 t; cvta.to.shared.u64 t, %1; cvt.u32.u64 %0, t; }" : "=r"(a) : "l"(p));
    return a;
}
__device__ __forceinline__ void cp16(uint32_t saddr, const void* g) {
    asm volatile("cp.async.cg.shared.global [%0], [%1], 16;" :: "r"(saddr), "l"(g));
}
__device__ __forceinline__ void cp_commit() {
    asm volatile("cp.async.commit_group;" ::: "memory");
}
__device__ __forceinline__ void ldsm_x4(uint32_t* r, uint32_t addr) {
    asm volatile("ldmatrix.sync.aligned.m8n8.x4.shared.b16 {%0,%1,%2,%3}, [%4];"
        : "=r"(r[0]), "=r"(r[1]), "=r"(r[2]), "=r"(r[3]) : "r"(addr));
}
__device__ __forceinline__ void ldsm_x4_trans(uint32_t* r, uint32_t addr) {
    asm volatile("ldmatrix.sync.aligned.m8n8.x4.trans.shared.b16 {%0,%1,%2,%3}, [%4];"
        : "=r"(r[0]), "=r"(r[1]), "=r"(r[2]), "=r"(r[3]) : "r"(addr));
}
__device__ __forceinline__ void mma_f16(float* c, const uint32_t* a, const uint32_t* b) {
    asm volatile("mma.sync.aligned.m16n8k16.row.col.f32.f16.f16.f32 "
        "{%0,%1,%2,%3}, {%4,%5,%6,%7}, {%8,%9}, {%0,%1,%2,%3};"
        : "+f"(c[0]), "+f"(c[1]), "+f"(c[2]), "+f"(c[3])
        : "r"(a[0]), "r"(a[1]), "r"(a[2]), "r"(a[3]), "r"(b[0]), "r"(b[1]));
}
__device__ __forceinline__ uint32_t pack_h2(float lo, float hi) {
    __half2 h = __floats2half2_rn(lo, hi);
    uint32_t u; memcpy(&u, &h, 4); return u;
}
__device__ __forceinline__ float ex2(float x) {
    float r;
    asm("ex2.approx.ftz.f32 %0, %1;" : "=f"(r) : "f"(x));
    return r;
}
__device__ __forceinline__ uint32_t h2ex2(uint32_t x) {
    uint32_t r;
    asm("ex2.approx.f16x2 %0, %1;" : "=r"(r) : "r"(x));
    return r;
}
__device__ __forceinline__ float2 h2_to_f2(uint32_t u) {
    __half2 h; memcpy(&h, &u, 4);
    return __half22float2(h);
}

// ---------------------------------------------------------------------------
// Fused prep kernel (blockIdx-partitioned)
// ---------------------------------------------------------------------------
#define PREP_X_BLOCKS  (M_ * K_ / (256 * 4))          // 8192
#define PREP_WQ_BLOCKS ((N_QKV / 32) * (K_ / 32))     // 3072
#define PREP_WP_BLOCKS ((C_ / 32) * (K_ / 32))        // 1024
#define PREP_BLOCKS (PREP_X_BLOCKS + PREP_WQ_BLOCKS + PREP_WP_BLOCKS)

__global__ __launch_bounds__(256) void prep_kernel(
    const float* __restrict__ x,
    const float* __restrict__ wqkv,
    const float* __restrict__ wproj)
{
    __shared__ float t[32][33];
    int bid = blockIdx.x;
    int tid = threadIdx.x;

    if (bid < PREP_X_BLOCKS) {
        int idx = (bid * 256 + tid) * 4;
        float4 v = *(const float4*)(x + idx);
        float vv[4] = {v.x, v.y, v.z, v.w};
        __half h[4];
#pragma unroll
        for (int i = 0; i < 4; i++) h[i] = __float2half_rn(vv[i]);
        *(uint2*)(g_xh + idx) = *(uint2*)h;
        return;
    }

    const float* W;
    __half* WT;
    int N, bx, by;
    if (bid < PREP_X_BLOCKS + PREP_WQ_BLOCKS) {
        int b = bid - PREP_X_BLOCKS;
        W = wqkv; WT = g_wqkvT; N = N_QKV;
        bx = b % (N_QKV / 32); by = b / (N_QKV / 32);
    } else {
        int b = bid - PREP_X_BLOCKS - PREP_WQ_BLOCKS;
        W = wproj; WT = g_wprojT; N = C_;
        bx = b % (C_ / 32); by = b / (C_ / 32);
    }
    int n0 = bx * 32, k0 = by * 32;
    int tx = tid & 31, ty = tid >> 5;
#pragma unroll
    for (int i = 0; i < 4; i++)
        t[ty + i * 8][tx] = W[(size_t)(k0 + ty + i * 8) * N + n0 + tx];
    __syncthreads();
#pragma unroll
    for (int i = 0; i < 4; i++) {
        int n = n0 + ty + i * 8;
        int k = k0 + tx;
        WT[(size_t)n * K_ + k] = __float2half_rn(t[tx][ty + i * 8]);
    }
}

// ---------------------------------------------------------------------------
// Tensor-core GEMM — R12 pipeline; warp tile 32(m)x64(n), 8 warps (4m x 2n),
// CTA tile 128x128. 6 LDSM per 16 MMAs per ks (2.67 MMA/LDSM).
// Stage 32KB (A16|B16), double-buffered -> 2 CTAs/SM.
// mode 0: scatter q (scaled by 0.125*log2e) / k / v; mode 1: f32 store.
// ---------------------------------------------------------------------------
#define STAGE_BYTES 32768
#define SM_GEMM_TOTAL (2 * STAGE_BYTES)   // 65536

__global__ __launch_bounds__(256, 2) void mma_gemm_kernel(
    const __half* __restrict__ Ah, const __half* __restrict__ Bm,
    float* __restrict__ out, int mode)
{
    extern __shared__ char smem[];
    uint32_t sbase = smem_to_u32(smem);

    int tid = threadIdx.x;
    int wid = tid >> 5;
    int lane = tid & 31;
    int wm = wid >> 1;          // 0..3 (m, 32 rows)
    int wn = wid & 1;           // 0..1 (n, 64 cols)

    int m0 = blockIdx.y * 128;
    int n0 = blockIdx.x * 128;

    float acc[2][8][4];
#pragma unroll
    for (int i = 0; i < 2; i++)
#pragma unroll
        for (int j = 0; j < 8; j++)
#pragma unroll
            for (int c = 0; c < 4; c++) acc[i][j][c] = 0.f;

    auto load_chunk = [&](int kt, int s) {
        uint32_t st = sbase + s * STAGE_BYTES;
#pragma unroll
        for (int p = 0; p < 4; p++) {
            int idx = tid + p * 256;
            int row = idx >> 3;
            int ch  = idx & 7;
            uint32_t so = SMEM_SWIZZLE_128B(row * 128 + ch * 16);
            size_t ka = (size_t)(m0 + row) * K_ + kt * 64 + ch * 8;
            size_t kb = (size_t)(n0 + row) * K_ + kt * 64 + ch * 8;
            cp16(st + so,         Ah + ka);
            cp16(st + 16384 + so, Bm + kb);
        }
        cp_commit();
    };

    load_chunk(0, 0);

    int a_row = lane & 15;
    int a_cb  = (lane >> 4) << 4;
    int bg     = lane >> 3;
    int bp_row = (lane & 7) + ((bg >> 1) << 3);
    int bp_cb  = (bg & 1) << 4;

    for (int kt = 0; kt < 16; kt++) {
        int s = kt & 1;
        if (kt + 1 < 16) {
            load_chunk(kt + 1, (kt + 1) & 1);
            asm volatile("cp.async.wait_group 1;" ::: "memory");
        } else {
            asm volatile("cp.async.wait_group 0;" ::: "memory");
        }
        __syncthreads();

        uint32_t sA = sbase + s * STAGE_BYTES;
        uint32_t sB = sA + 16384;

#pragma unroll
        for (int ks = 0; ks < 4; ks++) {
            int kB = ks * 32;
            uint32_t ah[2][4], bh[8][2];
#pragma unroll
            for (int i = 0; i < 2; i++) {
                uint32_t off = SMEM_SWIZZLE_128B((wm * 32 + i * 16 + a_row) * 128 + kB + a_cb);
                ldsm_x4(ah[i], sA + off);
            }
#pragma unroll
            for (int jp = 0; jp < 4; jp++) {
                uint32_t off = SMEM_SWIZZLE_128B((wn * 64 + jp * 16 + bp_row) * 128 + kB + bp_cb);
                uint32_t r4[4];
                ldsm_x4(r4, sB + off);
                bh[2 * jp][0] = r4[0]; bh[2 * jp][1] = r4[1];
                bh[2 * jp + 1][0] = r4[2]; bh[2 * jp + 1][1] = r4[3];
            }
#pragma unroll
            for (int i = 0; i < 2; i++)
#pragma unroll
                for (int j = 0; j < 8; j++) mma_f16(acc[i][j], ah[i], bh[j]);
        }
        __syncthreads();
    }

    int r4i = lane >> 2;
    int cp2 = (lane & 3) * 2;

    if (mode == 1) {
#pragma unroll
        for (int i = 0; i < 2; i++)
#pragma unroll
            for (int j = 0; j < 8; j++) {
                int n = n0 + wn * 64 + j * 8 + cp2;
#pragma unroll
                for (int rr = 0; rr < 2; rr++) {
                    int m = m0 + wm * 32 + i * 16 + r4i + rr * 8;
                    *(float2*)(out + (size_t)m * C_ + n) =
                        make_float2(acc[i][j][rr * 2], acc[i][j][rr * 2 + 1]);
                }
            }
    } else {
        int which = n0 >> 10;
        __half* dst = (which == 0) ? g_qh : (which == 1) ? g_kh : g_vh;
        float scale = (which == 0) ? (0.125f * LOG2E) : 1.0f;
#pragma unroll
        for (int i = 0; i < 2; i++)
#pragma unroll
            for (int j = 0; j < 8; j++) {
                int n = n0 + wn * 64 + j * 8 + cp2;
                int h = (n & 1023) >> 6;
                int d = n & 63;
#pragma unroll
                for (int rr = 0; rr < 2; rr++) {
                    int m = m0 + wm * 32 + i * 16 + r4i + rr * 8;
                    int b = m >> 11;
                    int t = m & 2047;
                    size_t off = (size_t)(((b << 4) + h) * T_ + t) * DH_ + d;
                    *(uint32_t*)(dst + off) =
                        pack_h2(acc[i][j][rr * 2] * scale, acc[i][j][rr * 2 + 1] * scale);
                }
            }
    }
}

// ---------------------------------------------------------------------------
// Tensor-core causal flash attention — KV tile 128 (two 64-halves per
// load+barrier), f16x2 softmax, log2 domain. R12 pipeline discipline.
// Smem: Q(16K) + 2 x (K16|V16) = 80K -> 2 CTAs/SM. LPT grid.
// ---------------------------------------------------------------------------
#define AS_Q  0
#define AS_KV 16384
#define KV_STAGE 32768        // K(16K) | V(16K)
#define AS_TOTAL (16384 + 2 * KV_STAGE)   // 81920

__global__ __launch_bounds__(256, 2) void attn_mma_kernel()
{
    extern __shared__ char smem[];
    uint32_t sb = smem_to_u32(smem);
    int tid = threadIdx.x;
    int wid = tid >> 5;
    int lane = tid & 31;

    int qt = 15 - blockIdx.y;     // longest first
    int bh = blockIdx.x;
    int q0 = qt * 128;
    size_t base = (size_t)bh * T_ * DH_;
    int njo = qt + 1;             // outer 128-kv tiles

#pragma unroll
    for (int p = 0; p < 4; p++) {
        int idx = tid + p * 256;
        int row = idx >> 3;
        int ch  = idx & 7;
        uint32_t so = SMEM_SWIZZLE_128B(row * 128 + ch * 16);
        cp16(sb + AS_Q + so, g_qh + base + (size_t)(q0 + row) * DH_ + ch * 8);
    }
    cp_commit();

    auto load_kv = [&](int jo, int s) {
        uint32_t st = sb + AS_KV + s * KV_STAGE;
#pragma unroll
        for (int p = 0; p < 4; p++) {
            int idx = tid + p * 256;
            int row = idx >> 3;
            int ch  = idx & 7;
            uint32_t so = SMEM_SWIZZLE_128B(row * 128 + ch * 16);
            size_t g = base + (size_t)(jo * 128 + row) * DH_ + ch * 8;
            cp16(st + so,         g_kh + g);
            cp16(st + 16384 + so, g_vh + g);
        }
        cp_commit();
    };

    load_kv(0, 0);

    uint32_t qh[4][4];
    float O[8][4];
#pragma unroll
    for (int dt = 0; dt < 8; dt++)
#pragma unroll
        for (int c = 0; c < 4; c++) O[dt][c] = 0.f;
    float m0r = -1e30f, m1r = -1e30f, l0r = 0.f, l1r = 0.f;

    int g4 = lane >> 2;
    int c2 = 2 * (lane & 3);
    int a_row = lane & 15;
    int a_cb  = (lane >> 4) << 4;
    int bg     = lane >> 3;
    int bp_row = (lane & 7) + ((bg >> 1) << 3);
    int bp_cb  = (bg & 1) << 4;
    int v_row = (lane & 7) + ((lane >> 3) & 1) * 8;
    int v_ct  = (lane >> 4) & 1;

    for (int jo = 0; jo < njo; jo++) {
        int s = jo & 1;
        if (jo + 1 < njo) {
            load_kv(jo + 1, (jo + 1) & 1);
            asm volatile("cp.async.wait_group 1;" ::: "memory");
        } else {
            asm volatile("cp.async.wait_group 0;" ::: "memory");
        }
        __syncthreads();

        if (jo == 0) {
#pragma unroll
            for (int ks = 0; ks < 4; ks++) {
                uint32_t off = SMEM_SWIZZLE_128B((wid * 16 + a_row) * 128 + ks * 32 + a_cb);
                ldsm_x4(qh[ks], sb + AS_Q + off);
            }
        }

        uint32_t stK = sb + AS_KV + s * KV_STAGE;
        uint32_t stV = stK + 16384;

#pragma unroll
        for (int half = 0; half < 2; half++) {
            int j = 2 * jo + half;
            int hrow = half * 64;

            float S[8][4];
#pragma unroll
            for (int jt = 0; jt < 8; jt++)
#pragma unroll
                for (int c = 0; c < 4; c++) S[jt][c] = 0.f;

#pragma unroll
            for (int jp = 0; jp < 4; jp++) {
#pragma unroll
                for (int ks = 0; ks < 4; ks++) {
                    uint32_t off = SMEM_SWIZZLE_128B((hrow + jp * 16 + bp_row) * 128 + ks * 32 + bp_cb);
                    uint32_t r4[4];
                    ldsm_x4(r4, stK + off);
                    mma_f16(S[2 * jp],     qh[ks], r4);
                    mma_f16(S[2 * jp + 1], qh[ks], r4 + 2);
                }
            }

            if (j >= 2 * qt) {
                int r0 = q0 + wid * 16 + g4;
                int cb = j * 64 + c2;
#pragma unroll
                for (int jt = 0; jt < 8; jt++) {
                    int c0 = cb + jt * 8;
                    if (c0 > r0)     S[jt][0] = -1e30f;
                    if (c0 + 1 > r0) S[jt][1] = -1e30f;
                    if (c0 > r0 + 8)     S[jt][2] = -1e30f;
                    if (c0 + 1 > r0 + 8) S[jt][3] = -1e30f;
                }
            }

            float mx0 = -1e30f, mx1 = -1e30f;
#pragma unroll
            for (int jt = 0; jt < 8; jt++) {
                mx0 = fmaxf(mx0, fmaxf(S[jt][0], S[jt][1]));
                mx1 = fmaxf(mx1, fmaxf(S[jt][2], S[jt][3]));
            }
            mx0 = fmaxf(mx0, __shfl_xor_sync(0xffffffffu, mx0, 1));
            mx0 = fmaxf(mx0, __shfl_xor_sync(0xffffffffu, mx0, 2));
            mx1 = fmaxf(mx1, __shfl_xor_sync(0xffffffffu, mx1, 1));
            mx1 = fmaxf(mx1, __shfl_xor_sync(0xffffffffu, mx1, 2));

            float mn0 = fmaxf(m0r, mx0), mn1 = fmaxf(m1r, mx1);
            float al0 = ex2(m0r - mn0), al1 = ex2(m1r - mn1);
            m0r = mn0; m1r = mn1;

            float s0 = 0.f, s1 = 0.f;
#pragma unroll
            for (int jt = 0; jt < 8; jt++) {
                uint32_t p0 = h2ex2(pack_h2(S[jt][0] - mn0, S[jt][1] - mn0));
                uint32_t p1 = h2ex2(pack_h2(S[jt][2] - mn1, S[jt][3] - mn1));
                float2 f0 = h2_to_f2(p0);
                float2 f1 = h2_to_f2(p1);
                s0 += f0.x + f0.y;
                s1 += f1.x + f1.y;
                S[jt][0] = __uint_as_float(p0);
                S[jt][2] = __uint_as_float(p1);
            }
            s0 += __shfl_xor_sync(0xffffffffu, s0, 1);
            s0 += __shfl_xor_sync(0xffffffffu, s0, 2);
            s1 += __shfl_xor_sync(0xffffffffu, s1, 1);
            s1 += __shfl_xor_sync(0xffffffffu, s1, 2);
            l0r = l0r * al0 + s0;
            l1r = l1r * al1 + s1;

#pragma unroll
            for (int dt = 0; dt < 8; dt++) {
                O[dt][0] *= al0; O[dt][1] *= al0;
                O[dt][2] *= al1; O[dt][3] *= al1;
            }

#pragma unroll
            for (int dtp = 0; dtp < 4; dtp++) {
#pragma unroll
                for (int ks2 = 0; ks2 < 4; ks2++) {
                    uint32_t ph[4] = {
                        __float_as_uint(S[2 * ks2][0]),     __float_as_uint(S[2 * ks2][2]),
                        __float_as_uint(S[2 * ks2 + 1][0]), __float_as_uint(S[2 * ks2 + 1][2])};
                    uint32_t off = SMEM_SWIZZLE_128B((hrow + ks2 * 16 + v_row) * 128 +
                                                     (2 * dtp + v_ct) * 16);
                    uint32_t r4[4];
                    ldsm_x4_trans(r4, stV + off);
                    mma_f16(O[2 * dtp],     ph, r4);
                    mma_f16(O[2 * dtp + 1], ph, r4 + 2);
                }
            }
        }
        __syncthreads();
    }

    float li0 = 1.f / l0r, li1 = 1.f / l1r;
    int b = bh >> 4, h = bh & 15;
    int r0 = q0 + wid * 16 + g4;
#pragma unroll
    for (int dt = 0; dt < 8; dt++) {
        int d = dt * 8 + c2;
        {
            size_t off = (size_t)(b * T_ + r0) * C_ + h * DH_ + d;
            *(uint32_t*)(g_yh + off) = pack_h2(O[dt][0] * li0, O[dt][1] * li0);
        }
        {
            size_t off = (size_t)(b * T_ + r0 + 8) * C_ + h * DH_ + d;
            *(uint32_t*)(g_yh + off) = pack_h2(O[dt][2] * li1, O[dt][3] * li1);
        }
    }
}

// ---------------------------------------------------------------------------
extern "C" void kernel_launch(void* const* d_in, const int* in_sizes, int n_in,
                              void* d_out, int out_size)
{
    const float* x      = (const float*)d_in[0];
    const float* w_qkv  = (const float*)d_in[1];
    const float* w_proj = (const float*)d_in[2];
    float* out = (float*)d_out;
    (void)in_sizes; (void)n_in; (void)out_size;

    cudaFuncSetAttribute(mma_gemm_kernel,
                         cudaFuncAttributeMaxDynamicSharedMemorySize, SM_GEMM_TOTAL);
    cudaFuncSetAttribute(attn_mma_kernel,
                         cudaFuncAttributeMaxDynamicSharedMemorySize, AS_TOTAL);

    __half *xh, *yh, *wq, *wp;
    cudaGetSymbolAddress((void**)&xh, g_xh);
    cudaGetSymbolAddress((void**)&yh, g_yh);
    cudaGetSymbolAddress((void**)&wq, g_wqkvT);
    cudaGetSymbolAddress((void**)&wp, g_wprojT);

    // fused prep
    prep_kernel<<<PREP_BLOCKS, 256>>>(x, w_qkv, w_proj);

    // QKV GEMM (32x64 warp tiles) with fused q-scale(+log2e) + scatter
    mma_gemm_kernel<<<dim3(N_QKV / 128, M_ / 128), 256, SM_GEMM_TOTAL>>>(
        xh, wq, nullptr, 0);

    // tensor-core causal flash attention (KV tile 128)
    attn_mma_kernel<<<dim3(B_ * H_, T_ / 128), 256, AS_TOTAL>>>();

    // output projection GEMM
    mma_gemm_kernel<<<dim3(C_ / 128, M_ / 128), 256, SM_GEMM_TOTAL>>>(
        yh, wp, out, 1);
}